// round 5
// baseline (speedup 1.0000x reference)
#include <cuda_runtime.h>
#include <cuda_bf16.h>
#include <stdint.h>

#define Bsz 4
#define Sq  4096
#define Dd  1024
#define BS  (Bsz * Sq)   // 16384

// ---------------- scratch (device globals — allocation is forbidden) ----------------
__device__ __align__(256) __nv_bfloat16 g_xh[(long long)BS * Dd];
__device__ __align__(256) __nv_bfloat16 g_xl[(long long)BS * Dd];
__device__ __align__(256) __nv_bfloat16 g_WkTh[Dd * Dd];
__device__ __align__(256) __nv_bfloat16 g_WkTl[Dd * Dd];
__device__ __align__(256) __nv_bfloat16 g_WvTh[Dd * Dd];
__device__ __align__(256) __nv_bfloat16 g_WvTl[Dd * Dd];
__device__ __align__(256) __nv_bfloat16 g_Wqh[Dd * Dd];
__device__ __align__(256) __nv_bfloat16 g_Wql[Dd * Dd];
__device__ __align__(256) __nv_bfloat16 g_Kh[(long long)BS * Dd];
__device__ __align__(256) __nv_bfloat16 g_Kl[(long long)BS * Dd];
__device__ __align__(256) __nv_bfloat16 g_Vh[(long long)BS * Dd];
__device__ __align__(256) __nv_bfloat16 g_Vl[(long long)BS * Dd];
__device__ __align__(256) __nv_bfloat16 g_KTh[(long long)BS * Dd];
__device__ __align__(256) __nv_bfloat16 g_KTl[(long long)BS * Dd];
__device__ __align__(256) __nv_bfloat16 g_VTh[(long long)BS * Dd];
__device__ __align__(256) __nv_bfloat16 g_VTl[(long long)BS * Dd];
__device__ __align__(256) float         g_G[(long long)Bsz * Dd * Dd];
__device__ __align__(256) float         g_s[Bsz * Dd];
__device__ __align__(256) float         g_r[Bsz * Dd];
__device__ __align__(256) __nv_bfloat16 g_Mh[(long long)Bsz * Dd * Dd];
__device__ __align__(256) __nv_bfloat16 g_Ml[(long long)Bsz * Dd * Dd];
__device__ __align__(256) __nv_bfloat16 g_W2Th[(long long)Bsz * Dd * Dd];
__device__ __align__(256) __nv_bfloat16 g_W2Tl[(long long)Bsz * Dd * Dd];

// ---------------- PTX helpers ----------------
__device__ __forceinline__ uint32_t smem_u32(const void* p) {
    uint32_t a;
    asm("{ .reg .u64 t; cvta.to.shared.u64 t, %1; cvt.u32.u64 %0, t; }" : "=r"(a) : "l"(p));
    return a;
}
__device__ __forceinline__ void cp16(uint32_t dst, const void* src) {
    asm volatile("cp.async.cg.shared.global [%0], [%1], 16;" :: "r"(dst), "l"(src));
}
__device__ __forceinline__ void cp_commit() { asm volatile("cp.async.commit_group;" ::: "memory"); }
__device__ __forceinline__ void cp_wait1()  { asm volatile("cp.async.wait_group 1;" ::: "memory"); }
__device__ __forceinline__ void cp_wait0()  { asm volatile("cp.async.wait_group 0;" ::: "memory"); }

__device__ __forceinline__ void ldsm_x4(uint32_t& r0, uint32_t& r1, uint32_t& r2, uint32_t& r3,
                                        uint32_t addr) {
    asm volatile("ldmatrix.sync.aligned.m8n8.x4.shared.b16 {%0,%1,%2,%3}, [%4];"
                 : "=r"(r0), "=r"(r1), "=r"(r2), "=r"(r3) : "r"(addr));
}
__device__ __forceinline__ void mma_bf16(float& c0, float& c1, float& c2, float& c3,
                                         uint32_t a0, uint32_t a1, uint32_t a2, uint32_t a3,
                                         uint32_t b0, uint32_t b1) {
    asm volatile(
        "mma.sync.aligned.m16n8k16.row.col.f32.bf16.bf16.f32 "
        "{%0,%1,%2,%3}, {%4,%5,%6,%7}, {%8,%9}, {%0,%1,%2,%3};"
        : "+f"(c0), "+f"(c1), "+f"(c2), "+f"(c3)
        : "r"(a0), "r"(a1), "r"(a2), "r"(a3), "r"(b0), "r"(b1));
}

// ---------------- split-bf16 HMMA GEMM: C[M,N] = (Ah+Al)(Bh+Bl)^T (+bias[n]) ----------------
// A: [M,K] row-major bf16 hi/lo.  B: [N,K] row-major bf16 hi/lo.
// CTA tile 128(M) x 256(N) x 32(K), 8 warps (2 along M x 4 along N), warp tile 64x64.
// SMEM layout: each logical row = 128 B: chunks (16B) 0-3 = hi k0..31, 4-7 = lo k0..31,
// physical chunk position = c ^ (row & 7)  -> conflict-free ldmatrix AND cp.async stores.
#define A_BYTES 16384                 // 128 rows * 128 B
#define B_BYTES 32768                 // 256 rows * 128 B
#define STG     (A_BYTES + B_BYTES)   // 49152
#define GEMM_DSMEM (2 * STG)          // 98304

__global__ __launch_bounds__(256, 1) void gemm_hmma(
    const __nv_bfloat16* __restrict__ Ah, const __nv_bfloat16* __restrict__ Al,
    const __nv_bfloat16* __restrict__ Bh, const __nv_bfloat16* __restrict__ Bl,
    const float* __restrict__ bias, float* __restrict__ Cf,
    __nv_bfloat16* __restrict__ Ch, __nv_bfloat16* __restrict__ Cl,
    int N, int Ktot,
    long long sA, long long sB, long long sBias, long long sC)
{
    extern __shared__ __align__(128) char smem[];
    const int tid = threadIdx.x;
    const int wid = tid >> 5, lid = tid & 31;
    const int bz = blockIdx.z;
    const long long bm = (long long)blockIdx.y * 128;
    const long long bn = (long long)blockIdx.x * 256;

    const __nv_bfloat16* gA[2] = { Ah + bz * sA + bm * Ktot, Al + bz * sA + bm * Ktot };
    const __nv_bfloat16* gB[2] = { Bh + bz * sB + bn * Ktot, Bl + bz * sB + bn * Ktot };
    const float* biasp = bias ? bias + bz * sBias : nullptr;

    const uint32_t sb = smem_u32(smem);

    // warp tile 64(M) x 64(N): 2 warps along M, 4 along N
    const int wm = (wid & 1) * 64;
    const int wn = (wid >> 1) * 64;

    float acc[4][8][4];
    #pragma unroll
    for (int a = 0; a < 4; a++)
        #pragma unroll
        for (int b = 0; b < 8; b++)
            #pragma unroll
            for (int c = 0; c < 4; c++) acc[a][b][c] = 0.f;

    // loader indices: id -> row = id>>3, chunk c = id&7 (c<4: hi plane, else lo)
    const int lr = tid >> 3, lc = tid & 7;
    const int lk = (lc & 3) * 8;          // global k element offset within chunk
    const int lpl = lc >> 2;              // plane
    auto load_chunk = [&](int p, int k0) {
        const uint32_t buf = sb + p * STG;
        // A: 128 rows -> 1024 chunks -> 4 iters of 256
        #pragma unroll
        for (int it = 0; it < 4; it++) {
            int r = lr + it * 32;
            cp16(buf + r * 128 + (((lc ^ r) & 7) << 4) + (lc & 8) * 0 + ((lc >> 3) << 0) * 0
                     + ((lc & 7) >= 0 ? 0 : 0) + (( (lc) ^ (r & 7)) != (lc ^ r) ? 0 : 0)
                 , gA[lpl] + (long long)r * Ktot + k0 + lk);
        }
        // B: 256 rows -> 2048 chunks -> 8 iters
        #pragma unroll
        for (int it = 0; it < 8; it++) {
            int r = lr + it * 32;
            cp16(buf + A_BYTES + r * 128 + ((lc ^ (r & 7)) << 4),
                 gB[lpl] + (long long)r * Ktot + k0 + lk);
        }
        cp_commit();
    };

    const int nc = Ktot >> 5;
    load_chunk(0, 0);

    // ldmatrix lane components
    const int a_row = wm + (lid & 15);          // + mb*16
    const int a_c   = (lid >> 4);               // + pl*4 + kk*2
    const int b_row = wn + (lid & 7) + ((lid >> 4) & 1) * 8;   // + nq*16
    const int b_c   = ((lid >> 3) & 1);         // + pl*4 + kk*2

    for (int i = 0; i < nc; i++) {
        if (i + 1 < nc) { load_chunk((i + 1) & 1, (i + 1) << 5); cp_wait1(); }
        else            { cp_wait0(); }
        __syncthreads();

        const uint32_t buf = sb + (i & 1) * STG;
        #pragma unroll
        for (int kk = 0; kk < 2; kk++) {
            uint32_t Af[2][4][4];
            #pragma unroll
            for (int pl = 0; pl < 2; pl++)
                #pragma unroll
                for (int mb = 0; mb < 4; mb++) {
                    int r = a_row + mb * 16;
                    int c = a_c + pl * 4 + kk * 2;
                    ldsm_x4(Af[pl][mb][0], Af[pl][mb][1], Af[pl][mb][2], Af[pl][mb][3],
                            buf + r * 128 + ((c ^ (r & 7)) << 4));
                }
            #pragma unroll
            for (int nq = 0; nq < 4; nq++) {
                uint32_t BH[4], BL[4];
                {
                    int r = b_row + nq * 16;
                    int ch = b_c + kk * 2;
                    int cl = ch + 4;
                    ldsm_x4(BH[0], BH[1], BH[2], BH[3],
                            buf + A_BYTES + r * 128 + ((ch ^ (r & 7)) << 4));
                    ldsm_x4(BL[0], BL[1], BL[2], BL[3],
                            buf + A_BYTES + r * 128 + ((cl ^ (r & 7)) << 4));
                }
                // pass-outer ordering: 8 independent accumulators between reuses
                #pragma unroll
                for (int mb = 0; mb < 4; mb++)
                    #pragma unroll
                    for (int half = 0; half < 2; half++) {
                        float* c = acc[mb][nq * 2 + half];
                        mma_bf16(c[0], c[1], c[2], c[3],
                                 Af[0][mb][0], Af[0][mb][1], Af[0][mb][2], Af[0][mb][3],
                                 BH[half * 2], BH[half * 2 + 1]);
                    }
                #pragma unroll
                for (int mb = 0; mb < 4; mb++)
                    #pragma unroll
                    for (int half = 0; half < 2; half++) {
                        float* c = acc[mb][nq * 2 + half];
                        mma_bf16(c[0], c[1], c[2], c[3],
                                 Af[0][mb][0], Af[0][mb][1], Af[0][mb][2], Af[0][mb][3],
                                 BL[half * 2], BL[half * 2 + 1]);
                    }
                #pragma unroll
                for (int mb = 0; mb < 4; mb++)
                    #pragma unroll
                    for (int half = 0; half < 2; half++) {
                        float* c = acc[mb][nq * 2 + half];
                        mma_bf16(c[0], c[1], c[2], c[3],
                                 Af[1][mb][0], Af[1][mb][1], Af[1][mb][2], Af[1][mb][3],
                                 BH[half * 2], BH[half * 2 + 1]);
                    }
            }
        }
        __syncthreads();
    }

    // epilogue
    const int er = lid >> 2;
    const int ec = (lid & 3) * 2;
    #pragma unroll
    for (int mb = 0; mb < 4; mb++) {
        #pragma unroll
        for (int nb = 0; nb < 8; nb++) {
            const float* c = acc[mb][nb];
            long long col = bn + wn + nb * 8 + ec;
            float bx = 0.f, by = 0.f;
            if (biasp) { bx = biasp[col]; by = biasp[col + 1]; }
            long long r0 = bm + wm + mb * 16 + er;
            float v0 = c[0] + bx, v1 = c[1] + by;
            float v2 = c[2] + bx, v3 = c[3] + by;
            if (Cf) {
                float* Cb = Cf + bz * sC;
                *reinterpret_cast<float2*>(Cb + r0 * N + col) = make_float2(v0, v1);
                *reinterpret_cast<float2*>(Cb + (r0 + 8) * N + col) = make_float2(v2, v3);
            } else {
                __nv_bfloat16 h0 = __float2bfloat16(v0), h1 = __float2bfloat16(v1);
                __nv_bfloat16 h2 = __float2bfloat16(v2), h3 = __float2bfloat16(v3);
                __nv_bfloat162 hp0 = { h0, h1 }, hp1 = { h2, h3 };
                __nv_bfloat162 lp0 = { __float2bfloat16(v0 - __bfloat162float(h0)),
                                       __float2bfloat16(v1 - __bfloat162float(h1)) };
                __nv_bfloat162 lp1 = { __float2bfloat16(v2 - __bfloat162float(h2)),
                                       __float2bfloat16(v3 - __bfloat162float(h3)) };
                __nv_bfloat16* Hb = Ch + bz * sC;
                __nv_bfloat16* Lb = Cl + bz * sC;
                *reinterpret_cast<__nv_bfloat162*>(Hb + r0 * N + col) = hp0;
                *reinterpret_cast<__nv_bfloat162*>(Hb + (r0 + 8) * N + col) = hp1;
                *reinterpret_cast<__nv_bfloat162*>(Lb + r0 * N + col) = lp0;
                *reinterpret_cast<__nv_bfloat162*>(Lb + (r0 + 8) * N + col) = lp1;
            }
        }
    }
}

// ---------------- prep kernels ----------------
__global__ void split_conv(const float* __restrict__ s, __nv_bfloat16* __restrict__ h,
                           __nv_bfloat16* __restrict__ l, long long n)
{
    long long i = (long long)blockIdx.x * blockDim.x + threadIdx.x;
    if (i < n) {
        float v = s[i];
        __nv_bfloat16 hi = __float2bfloat16(v);
        h[i] = hi;
        l[i] = __float2bfloat16(v - __bfloat162float(hi));
    }
}

__global__ void transpose_split(const float* __restrict__ src,
                                __nv_bfloat16* __restrict__ dh, __nv_bfloat16* __restrict__ dl,
                                int R, int C)
{
    __shared__ float t[32][33];
    int c0 = blockIdx.x * 32, r0 = blockIdx.y * 32;
    int tx = threadIdx.x, ty = threadIdx.y;
    #pragma unroll
    for (int k = 0; k < 32; k += 8)
        t[ty + k][tx] = src[(long long)(r0 + ty + k) * C + c0 + tx];
    __syncthreads();
    #pragma unroll
    for (int k = 0; k < 32; k += 8) {
        float v = t[tx][ty + k];
        __nv_bfloat16 hi = __float2bfloat16(v);
        long long o = (long long)(c0 + ty + k) * R + r0 + tx;
        dh[o] = hi;
        dl[o] = __float2bfloat16(v - __bfloat162float(hi));
    }
}

__global__ void transpose_pair(const __nv_bfloat16* __restrict__ sh,
                               const __nv_bfloat16* __restrict__ sl,
                               __nv_bfloat16* __restrict__ dh, __nv_bfloat16* __restrict__ dl,
                               int R, int C, long long sIn, long long sOut)
{
    __shared__ __nv_bfloat16 th[64][65], tl[64][65];
    int b = blockIdx.z;
    sh += (long long)b * sIn; sl += (long long)b * sIn;
    dh += (long long)b * sOut; dl += (long long)b * sOut;
    int c0 = blockIdx.x * 64, r0 = blockIdx.y * 64;
    int tid = threadIdx.x;
    #pragma unroll
    for (int it = 0; it < 8; it++) {
        int id = tid + it * 256;
        int row = id >> 5, cp = (id & 31) * 2;
        long long src = (long long)(r0 + row) * C + c0 + cp;
        __nv_bfloat162 vh = *reinterpret_cast<const __nv_bfloat162*>(sh + src);
        __nv_bfloat162 vl = *reinterpret_cast<const __nv_bfloat162*>(sl + src);
        th[row][cp] = vh.x; th[row][cp + 1] = vh.y;
        tl[row][cp] = vl.x; tl[row][cp + 1] = vl.y;
    }
    __syncthreads();
    #pragma unroll
    for (int it = 0; it < 8; it++) {
        int id = tid + it * 256;
        int cc = id >> 5, rp = (id & 31) * 2;
        long long dst = (long long)(c0 + cc) * R + r0 + rp;
        __nv_bfloat162 vh = { th[rp][cc], th[rp + 1][cc] };
        __nv_bfloat162 vl = { tl[rp][cc], tl[rp + 1][cc] };
        *reinterpret_cast<__nv_bfloat162*>(dh + dst) = vh;
        *reinterpret_cast<__nv_bfloat162*>(dl + dst) = vl;
    }
}

__global__ void zero_s(float* p) { p[blockIdx.x * 256 + threadIdx.x] = 0.f; }

__global__ void reduce_s2(const float* __restrict__ G, float* __restrict__ s)
{
    int b = blockIdx.z;
    int n = blockIdx.x * 256 + threadIdx.x;
    int j0 = blockIdx.y * 128;
    const float* Gb = G + ((long long)b << 20);
    float acc = 0.f;
    #pragma unroll 4
    for (int j = j0; j < j0 + 128; j++)
        acc += Gb[((long long)j << 10) + ((n - j) & (Dd - 1))];
    atomicAdd(&s[b * Dd + n], acc);
}

__global__ void build_M_split(const float* __restrict__ s,
                              __nv_bfloat16* __restrict__ h, __nv_bfloat16* __restrict__ l)
{
    int b = blockIdx.z, k = blockIdx.y;
    int n = blockIdx.x * 256 + threadIdx.x;
    float v = s[b * Dd + ((k + n) & (Dd - 1))];
    __nv_bfloat16 hi = __float2bfloat16(v);
    long long o = ((long long)b << 20) + ((long long)k << 10) + n;
    h[o] = hi;
    l[o] = __float2bfloat16(v - __bfloat162float(hi));
}

__global__ void compute_r(const float* __restrict__ s, const float* __restrict__ bq,
                          float* __restrict__ r)
{
    int b = blockIdx.y;
    int n = blockIdx.x * 256 + threadIdx.x;
    float acc = 0.f;
    for (int m = 0; m < Dd; m++)
        acc += bq[m] * s[b * Dd + ((m + n) & (Dd - 1))];
    r[b * Dd + n] = acc;
}

// ---------------- launcher ----------------
extern "C" void kernel_launch(void* const* d_in, const int* in_sizes, int n_in,
                              void* d_out, int out_size)
{
    const float* x  = (const float*)d_in[0];
    const float* Wq = (const float*)d_in[1];
    const float* bq = (const float*)d_in[2];
    const float* Wk = (const float*)d_in[3];
    const float* bk = (const float*)d_in[4];
    const float* Wv = (const float*)d_in[5];
    const float* bv = (const float*)d_in[6];
    float* out = (float*)d_out;

    __nv_bfloat16 *xh, *xl, *WkTh, *WkTl, *WvTh, *WvTl, *Wqh, *Wql;
    __nv_bfloat16 *Kh, *Kl, *Vh, *Vl, *KTh, *KTl, *VTh, *VTl, *Mh, *Ml, *W2Th, *W2Tl;
    float *G, *s, *r;
    cudaGetSymbolAddress((void**)&xh, g_xh);     cudaGetSymbolAddress((void**)&xl, g_xl);
    cudaGetSymbolAddress((void**)&WkTh, g_WkTh); cudaGetSymbolAddress((void**)&WkTl, g_WkTl);
    cudaGetSymbolAddress((void**)&WvTh, g_WvTh); cudaGetSymbolAddress((void**)&WvTl, g_WvTl);
    cudaGetSymbolAddress((void**)&Wqh, g_Wqh);   cudaGetSymbolAddress((void**)&Wql, g_Wql);
    cudaGetSymbolAddress((void**)&Kh, g_Kh);     cudaGetSymbolAddress((void**)&Kl, g_Kl);
    cudaGetSymbolAddress((void**)&Vh, g_Vh);     cudaGetSymbolAddress((void**)&Vl, g_Vl);
    cudaGetSymbolAddress((void**)&KTh, g_KTh);   cudaGetSymbolAddress((void**)&KTl, g_KTl);
    cudaGetSymbolAddress((void**)&VTh, g_VTh);   cudaGetSymbolAddress((void**)&VTl, g_VTl);
    cudaGetSymbolAddress((void**)&G, g_G);       cudaGetSymbolAddress((void**)&s, g_s);
    cudaGetSymbolAddress((void**)&r, g_r);
    cudaGetSymbolAddress((void**)&Mh, g_Mh);     cudaGetSymbolAddress((void**)&Ml, g_Ml);
    cudaGetSymbolAddress((void**)&W2Th, g_W2Th); cudaGetSymbolAddress((void**)&W2Tl, g_W2Tl);

    cudaFuncSetAttribute(gemm_hmma, cudaFuncAttributeMaxDynamicSharedMemorySize, GEMM_DSMEM);

    const long long nBS = (long long)BS * Dd;       // 16M
    const long long dd  = (long long)Dd * Dd;       // 1M
    const long long sd  = (long long)Sq * Dd;       // 4M

    // 0) input conversion
    split_conv<<<(unsigned)((nBS + 255) / 256), 256>>>(x, xh, xl, nBS);
    transpose_split<<<dim3(Dd / 32, Dd / 32), dim3(32, 8)>>>(Wk, WkTh, WkTl, Dd, Dd);
    transpose_split<<<dim3(Dd / 32, Dd / 32), dim3(32, 8)>>>(Wv, WvTh, WvTl, Dd, Dd);
    split_conv<<<(unsigned)((dd + 255) / 256), 256>>>(Wq, Wqh, Wql, dd);

    // 1) K = x@Wk + bk ; V = x@Wv + bv  -> bf16 hi/lo [BS, D]
    gemm_hmma<<<dim3(Dd / 256, BS / 128, 1), 256, GEMM_DSMEM>>>(
        xh, xl, WkTh, WkTl, bk, nullptr, Kh, Kl, Dd, Dd, 0, 0, 0, 0);
    gemm_hmma<<<dim3(Dd / 256, BS / 128, 1), 256, GEMM_DSMEM>>>(
        xh, xl, WvTh, WvTl, bv, nullptr, Vh, Vl, Dd, Dd, 0, 0, 0, 0);

    // 2) per-batch transpose: [Sq, D] -> [D, Sq]
    transpose_pair<<<dim3(Dd / 64, Sq / 64, Bsz), 256>>>(Kh, Kl, KTh, KTl, Sq, Dd, sd, sd);
    transpose_pair<<<dim3(Dd / 64, Sq / 64, Bsz), 256>>>(Vh, Vl, VTh, VTl, Sq, Dd, sd, sd);

    // 3) G_b = K_b^T @ V_b  (M=N=1024, K=4096, batched)
    gemm_hmma<<<dim3(Dd / 256, Dd / 128, Bsz), 256, GEMM_DSMEM>>>(
        KTh, KTl, VTh, VTl, nullptr, G, nullptr, nullptr, Dd, Sq, sd, sd, 0, dd);

    // 4) s_b = circular anti-diagonal sum of G_b
    zero_s<<<Bsz * Dd / 256, 256>>>(s);
    reduce_s2<<<dim3(Dd / 256, 8, Bsz), 256>>>(G, s);

    // 5) M_b (bf16 hi/lo), r_b = bq @ M_b
    build_M_split<<<dim3(Dd / 256, Dd, Bsz), 256>>>(s, Mh, Ml);
    compute_r<<<dim3(Dd / 256, Bsz), 256>>>(s, bq, r);

    // 6) W2T_b = M_b @ Wq^T -> bf16 hi/lo directly (M symmetric; see R2 derivation)
    gemm_hmma<<<dim3(Dd / 256, Dd / 128, Bsz), 256, GEMM_DSMEM>>>(
        Mh, Ml, Wqh, Wql, nullptr, nullptr, W2Th, W2Tl, Dd, Dd, dd, 0, 0, dd);

    // 7) out_b = x_b @ W2_b + r_b
    gemm_hmma<<<dim3(Dd / 256, Sq / 128, Bsz), 256, GEMM_DSMEM>>>(
        xh, xl, W2Th, W2Tl, r, out, nullptr, nullptr, Dd, Dd, sd, dd, Dd, sd);
}

// round 6
// speedup vs baseline: 1.5720x; 1.5720x over previous
#include <cuda_runtime.h>
#include <cuda_fp16.h>
#include <stdint.h>

#define Bsz 4
#define Sq  4096
#define Dd  1024
#define BS  (Bsz * Sq)   // 16384

// ---------------- scratch (device globals — allocation is forbidden) ----------------
__device__ __align__(256) __half g_xh[(long long)BS * Dd];
__device__ __align__(256) __half g_xl[(long long)BS * Dd];
__device__ __align__(256) __half g_WkTs[Dd * Dd];
__device__ __align__(256) __half g_WvTs[Dd * Dd];
__device__ __align__(256) __half g_Wqs[Dd * Dd];
__device__ __align__(256) __half g_Kh[(long long)BS * Dd];
__device__ __align__(256) __half g_Kl[(long long)BS * Dd];
__device__ __align__(256) __half g_Vs[(long long)BS * Dd];
__device__ __align__(256) __half g_KTh[(long long)BS * Dd];
__device__ __align__(256) __half g_KTl[(long long)BS * Dd];
__device__ __align__(256) __half g_VTs[(long long)BS * Dd];
__device__ __align__(256) float  g_G[(long long)Bsz * Dd * Dd];
__device__ __align__(256) float  g_s[Bsz * Dd];
__device__ __align__(256) float  g_r[Bsz * Dd];
__device__ __align__(256) __half g_Mh[(long long)Bsz * Dd * Dd];
__device__ __align__(256) __half g_Ml[(long long)Bsz * Dd * Dd];
__device__ __align__(256) __half g_W2Ts[(long long)Bsz * Dd * Dd];

// ---------------- PTX helpers ----------------
__device__ __forceinline__ uint32_t smem_u32(const void* p) {
    uint32_t a;
    asm("{ .reg .u64 t; cvta.to.shared.u64 t, %1; cvt.u32.u64 %0, t; }" : "=r"(a) : "l"(p));
    return a;
}
__device__ __forceinline__ void cp16(uint32_t dst, const void* src) {
    asm volatile("cp.async.cg.shared.global [%0], [%1], 16;" :: "r"(dst), "l"(src));
}
__device__ __forceinline__ void cp_commit() { asm volatile("cp.async.commit_group;" ::: "memory"); }
__device__ __forceinline__ void cp_wait1()  { asm volatile("cp.async.wait_group 1;" ::: "memory"); }
__device__ __forceinline__ void cp_wait0()  { asm volatile("cp.async.wait_group 0;" ::: "memory"); }

__device__ __forceinline__ void ldsm_x4(uint32_t& r0, uint32_t& r1, uint32_t& r2, uint32_t& r3,
                                        uint32_t addr) {
    asm volatile("ldmatrix.sync.aligned.m8n8.x4.shared.b16 {%0,%1,%2,%3}, [%4];"
                 : "=r"(r0), "=r"(r1), "=r"(r2), "=r"(r3) : "r"(addr));
}
__device__ __forceinline__ void mma_fp16(float& c0, float& c1, float& c2, float& c3,
                                         uint32_t a0, uint32_t a1, uint32_t a2, uint32_t a3,
                                         uint32_t b0, uint32_t b1) {
    asm volatile(
        "mma.sync.aligned.m16n8k16.row.col.f32.f16.f16.f32 "
        "{%0,%1,%2,%3}, {%4,%5,%6,%7}, {%8,%9}, {%0,%1,%2,%3};"
        : "+f"(c0), "+f"(c1), "+f"(c2), "+f"(c3)
        : "r"(a0), "r"(a1), "r"(a2), "r"(a3), "r"(b0), "r"(b1));
}

// ---------------- 2-pass split-fp16 HMMA GEMM: C[M,N] = (Ah+Al) @ Bs^T (+bias[n]) -----------
// A: [M,K] row-major fp16, two planes (hi, lo).  B: [N,K] row-major fp16 single plane.
// CTA tile 128(M) x 256(N) x 64(K), 8 warps (2 M x 4 N), warp tile 64x64.
// SMEM row = 128B = 64 fp16 of k. 16B chunk c at physical slot c ^ (row & 7): conflict-free.
// Output modes: Cf fp32 | (Ch,Cl) fp16 hi/lo | Ch fp16 single. Bias applied in fp32 always.
#define A_BYTES 32768                 // 2 planes * 128 rows * 128 B
#define B_BYTES 32768                 // 256 rows * 128 B
#define STG     (A_BYTES + B_BYTES)   // 65536
#define GEMM_DSMEM (2 * STG)          // 131072

__global__ __launch_bounds__(256, 1) void gemm_hmma(
    const __half* __restrict__ Ah, const __half* __restrict__ Al,
    const __half* __restrict__ Bs,
    const float* __restrict__ bias, float* __restrict__ Cf,
    __half* __restrict__ Ch, __half* __restrict__ Cl,
    int N, int Ktot,
    long long sA, long long sB, long long sBias, long long sC)
{
    extern __shared__ __align__(128) char smem[];
    const int tid = threadIdx.x;
    const int wid = tid >> 5, lid = tid & 31;
    const int bz = blockIdx.z;
    const long long bm = (long long)blockIdx.y * 128;
    const long long bn = (long long)blockIdx.x * 256;

    const __half* gA[2] = { Ah + bz * sA + bm * Ktot, Al + bz * sA + bm * Ktot };
    const __half* gB = Bs + bz * sB + bn * Ktot;
    const float* biasp = bias ? bias + bz * sBias : nullptr;

    const uint32_t sb = smem_u32(smem);

    const int wm = (wid & 1) * 64;      // 2 warps along M
    const int wn = (wid >> 1) * 64;     // 4 warps along N

    float acc[4][8][4];
    #pragma unroll
    for (int a = 0; a < 4; a++)
        #pragma unroll
        for (int b = 0; b < 8; b++)
            #pragma unroll
            for (int c = 0; c < 4; c++) acc[a][b][c] = 0.f;

    auto load_chunk = [&](int p, int k0) {
        const uint32_t buf = sb + p * STG;
        // A: 2 planes x 128 rows x 8 chunks = 2048 chunks
        #pragma unroll
        for (int it = 0; it < 8; it++) {
            int id = tid + it * 256;
            int pl = id >> 10, rem = id & 1023;
            int r = rem >> 3, c = rem & 7;
            cp16(buf + pl * 16384 + r * 128 + (((c ^ r) & 7) << 4),
                 gA[pl] + (long long)r * Ktot + k0 + c * 8);
        }
        // B: 256 rows x 8 chunks = 2048 chunks
        #pragma unroll
        for (int it = 0; it < 8; it++) {
            int id = tid + it * 256;
            int r = id >> 3, c = id & 7;
            cp16(buf + A_BYTES + r * 128 + ((c ^ (r & 7)) << 4),
                 gB + (long long)r * Ktot + k0 + c * 8);
        }
        cp_commit();
    };

    const int nc = Ktot >> 6;
    load_chunk(0, 0);

    const int a_row = wm + (lid & 15);
    const int a_hi  = lid >> 4;
    const int b_row = wn + (lid & 7) + ((lid >> 4) & 1) * 8;
    const int b_hi  = (lid >> 3) & 1;

    for (int i = 0; i < nc; i++) {
        if (i + 1 < nc) { load_chunk((i + 1) & 1, (i + 1) << 6); cp_wait1(); }
        else            { cp_wait0(); }
        __syncthreads();

        const uint32_t buf = sb + (i & 1) * STG;
        #pragma unroll
        for (int kk = 0; kk < 4; kk++) {
            uint32_t Af[2][4][4];
            #pragma unroll
            for (int pl = 0; pl < 2; pl++)
                #pragma unroll
                for (int mb = 0; mb < 4; mb++) {
                    int r = a_row + mb * 16;
                    int c = kk * 2 + a_hi;
                    ldsm_x4(Af[pl][mb][0], Af[pl][mb][1], Af[pl][mb][2], Af[pl][mb][3],
                            buf + pl * 16384 + r * 128 + ((c ^ (r & 7)) << 4));
                }
            uint32_t Bf[4][4];
            #pragma unroll
            for (int nq = 0; nq < 4; nq++) {
                int r = b_row + nq * 16;
                int c = kk * 2 + b_hi;
                ldsm_x4(Bf[nq][0], Bf[nq][1], Bf[nq][2], Bf[nq][3],
                        buf + A_BYTES + r * 128 + ((c ^ (r & 7)) << 4));
            }
            // pass 0: hi plane — 32 independent MMAs
            #pragma unroll
            for (int mb = 0; mb < 4; mb++)
                #pragma unroll
                for (int nq = 0; nq < 4; nq++)
                    #pragma unroll
                    for (int half = 0; half < 2; half++) {
                        float* c = acc[mb][nq * 2 + half];
                        mma_fp16(c[0], c[1], c[2], c[3],
                                 Af[0][mb][0], Af[0][mb][1], Af[0][mb][2], Af[0][mb][3],
                                 Bf[nq][half * 2], Bf[nq][half * 2 + 1]);
                    }
            // pass 1: lo plane
            #pragma unroll
            for (int mb = 0; mb < 4; mb++)
                #pragma unroll
                for (int nq = 0; nq < 4; nq++)
                    #pragma unroll
                    for (int half = 0; half < 2; half++) {
                        float* c = acc[mb][nq * 2 + half];
                        mma_fp16(c[0], c[1], c[2], c[3],
                                 Af[1][mb][0], Af[1][mb][1], Af[1][mb][2], Af[1][mb][3],
                                 Bf[nq][half * 2], Bf[nq][half * 2 + 1]);
                    }
        }
        __syncthreads();
    }

    // epilogue
    const int er = lid >> 2;
    const int ec = (lid & 3) * 2;
    #pragma unroll
    for (int mb = 0; mb < 4; mb++) {
        #pragma unroll
        for (int nb = 0; nb < 8; nb++) {
            const float* c = acc[mb][nb];
            long long col = bn + wn + nb * 8 + ec;
            float bx = 0.f, by = 0.f;
            if (biasp) { bx = biasp[col]; by = biasp[col + 1]; }
            long long r0 = bm + wm + mb * 16 + er;
            float v0 = c[0] + bx, v1 = c[1] + by;
            float v2 = c[2] + bx, v3 = c[3] + by;
            if (Cf) {
                float* Cb = Cf + bz * sC;
                *reinterpret_cast<float2*>(Cb + r0 * N + col) = make_float2(v0, v1);
                *reinterpret_cast<float2*>(Cb + (r0 + 8) * N + col) = make_float2(v2, v3);
            } else if (Cl) {
                __half h0 = __float2half(v0), h1 = __float2half(v1);
                __half h2 = __float2half(v2), h3 = __float2half(v3);
                __half2 hp0 = { h0, h1 }, hp1 = { h2, h3 };
                __half2 lp0 = { __float2half(v0 - __half2float(h0)),
                                __float2half(v1 - __half2float(h1)) };
                __half2 lp1 = { __float2half(v2 - __half2float(h2)),
                                __float2half(v3 - __half2float(h3)) };
                __half* Hb = Ch + bz * sC;
                __half* Lb = Cl + bz * sC;
                *reinterpret_cast<__half2*>(Hb + r0 * N + col) = hp0;
                *reinterpret_cast<__half2*>(Hb + (r0 + 8) * N + col) = hp1;
                *reinterpret_cast<__half2*>(Lb + r0 * N + col) = lp0;
                *reinterpret_cast<__half2*>(Lb + (r0 + 8) * N + col) = lp1;
            } else {
                __half2 s0 = { __float2half(v0), __float2half(v1) };
                __half2 s1 = { __float2half(v2), __float2half(v3) };
                __half* Hb = Ch + bz * sC;
                *reinterpret_cast<__half2*>(Hb + r0 * N + col) = s0;
                *reinterpret_cast<__half2*>(Hb + (r0 + 8) * N + col) = s1;
            }
        }
    }
}

// ---------------- prep kernels ----------------
__global__ void split_conv_f16(const float* __restrict__ s, __half* __restrict__ h,
                               __half* __restrict__ l, long long n)
{
    long long i = (long long)blockIdx.x * blockDim.x + threadIdx.x;
    if (i < n) {
        float v = s[i];
        __half hi = __float2half(v);
        h[i] = hi;
        l[i] = __float2half(v - __half2float(hi));
    }
}

__global__ void conv_f16(const float* __restrict__ s, __half* __restrict__ d, long long n)
{
    long long i = (long long)blockIdx.x * blockDim.x + threadIdx.x;
    if (i < n) d[i] = __float2half(s[i]);
}

// fp32 [R,C] -> fp16 [C,R] single plane (weights)
__global__ void transpose_conv_f16(const float* __restrict__ src, __half* __restrict__ dst,
                                   int R, int C)
{
    __shared__ float t[32][33];
    int c0 = blockIdx.x * 32, r0 = blockIdx.y * 32;
    int tx = threadIdx.x, ty = threadIdx.y;
    #pragma unroll
    for (int k = 0; k < 32; k += 8)
        t[ty + k][tx] = src[(long long)(r0 + ty + k) * C + c0 + tx];
    __syncthreads();
    #pragma unroll
    for (int k = 0; k < 32; k += 8)
        dst[(long long)(c0 + ty + k) * R + r0 + tx] = __float2half(t[tx][ty + k]);
}

// fp16 pair [R,C] -> [C,R], batched
__global__ void transpose_pair_f16(const __half* __restrict__ sh, const __half* __restrict__ sl,
                                   __half* __restrict__ dh, __half* __restrict__ dl,
                                   int R, int C, long long sIn, long long sOut)
{
    __shared__ __half th[64][65], tl[64][65];
    int b = blockIdx.z;
    sh += (long long)b * sIn; sl += (long long)b * sIn;
    dh += (long long)b * sOut; dl += (long long)b * sOut;
    int c0 = blockIdx.x * 64, r0 = blockIdx.y * 64;
    int tid = threadIdx.x;
    #pragma unroll
    for (int it = 0; it < 8; it++) {
        int id = tid + it * 256;
        int row = id >> 5, cp = (id & 31) * 2;
        long long src = (long long)(r0 + row) * C + c0 + cp;
        __half2 vh = *reinterpret_cast<const __half2*>(sh + src);
        __half2 vl = *reinterpret_cast<const __half2*>(sl + src);
        th[row][cp] = vh.x; th[row][cp + 1] = vh.y;
        tl[row][cp] = vl.x; tl[row][cp + 1] = vl.y;
    }
    __syncthreads();
    #pragma unroll
    for (int it = 0; it < 8; it++) {
        int id = tid + it * 256;
        int cc = id >> 5, rp = (id & 31) * 2;
        long long dst = (long long)(c0 + cc) * R + r0 + rp;
        __half2 vh = { th[rp][cc], th[rp + 1][cc] };
        __half2 vl = { tl[rp][cc], tl[rp + 1][cc] };
        *reinterpret_cast<__half2*>(dh + dst) = vh;
        *reinterpret_cast<__half2*>(dl + dst) = vl;
    }
}

// fp16 single [R,C] -> [C,R], batched
__global__ void transpose_f16(const __half* __restrict__ s, __half* __restrict__ d,
                              int R, int C, long long sIn, long long sOut)
{
    __shared__ __half t[64][65];
    int b = blockIdx.z;
    s += (long long)b * sIn; d += (long long)b * sOut;
    int c0 = blockIdx.x * 64, r0 = blockIdx.y * 64;
    int tid = threadIdx.x;
    #pragma unroll
    for (int it = 0; it < 8; it++) {
        int id = tid + it * 256;
        int row = id >> 5, cp = (id & 31) * 2;
        __half2 v = *reinterpret_cast<const __half2*>(s + (long long)(r0 + row) * C + c0 + cp);
        t[row][cp] = v.x; t[row][cp + 1] = v.y;
    }
    __syncthreads();
    #pragma unroll
    for (int it = 0; it < 8; it++) {
        int id = tid + it * 256;
        int cc = id >> 5, rp = (id & 31) * 2;
        __half2 v = { t[rp][cc], t[rp + 1][cc] };
        *reinterpret_cast<__half2*>(d + (long long)(c0 + cc) * R + r0 + rp) = v;
    }
}

__global__ void zero_s(float* p) { p[blockIdx.x * 256 + threadIdx.x] = 0.f; }

__global__ void reduce_s2(const float* __restrict__ G, float* __restrict__ s)
{
    int b = blockIdx.z;
    int n = blockIdx.x * 256 + threadIdx.x;
    int j0 = blockIdx.y * 128;
    const float* Gb = G + ((long long)b << 20);
    float acc = 0.f;
    #pragma unroll 4
    for (int j = j0; j < j0 + 128; j++)
        acc += Gb[((long long)j << 10) + ((n - j) & (Dd - 1))];
    atomicAdd(&s[b * Dd + n], acc);
}

__global__ void build_M_f16(const float* __restrict__ s,
                            __half* __restrict__ h, __half* __restrict__ l)
{
    int b = blockIdx.z, k = blockIdx.y;
    int n = blockIdx.x * 256 + threadIdx.x;
    float v = s[b * Dd + ((k + n) & (Dd - 1))];
    __half hi = __float2half(v);
    long long o = ((long long)b << 20) + ((long long)k << 10) + n;
    h[o] = hi;
    l[o] = __float2half(v - __half2float(hi));
}

__global__ void compute_r(const float* __restrict__ s, const float* __restrict__ bq,
                          float* __restrict__ r)
{
    int b = blockIdx.y;
    int n = blockIdx.x * 256 + threadIdx.x;
    float acc = 0.f;
    for (int m = 0; m < Dd; m++)
        acc += bq[m] * s[b * Dd + ((m + n) & (Dd - 1))];
    r[b * Dd + n] = acc;
}

// ---------------- launcher ----------------
extern "C" void kernel_launch(void* const* d_in, const int* in_sizes, int n_in,
                              void* d_out, int out_size)
{
    const float* x  = (const float*)d_in[0];
    const float* Wq = (const float*)d_in[1];
    const float* bq = (const float*)d_in[2];
    const float* Wk = (const float*)d_in[3];
    const float* bk = (const float*)d_in[4];
    const float* Wv = (const float*)d_in[5];
    const float* bv = (const float*)d_in[6];
    float* out = (float*)d_out;

    __half *xh, *xl, *WkTs, *WvTs, *Wqs, *Kh, *Kl, *Vs, *KTh, *KTl, *VTs, *Mh, *Ml, *W2Ts;
    float *G, *s, *r;
    cudaGetSymbolAddress((void**)&xh, g_xh);     cudaGetSymbolAddress((void**)&xl, g_xl);
    cudaGetSymbolAddress((void**)&WkTs, g_WkTs); cudaGetSymbolAddress((void**)&WvTs, g_WvTs);
    cudaGetSymbolAddress((void**)&Wqs, g_Wqs);
    cudaGetSymbolAddress((void**)&Kh, g_Kh);     cudaGetSymbolAddress((void**)&Kl, g_Kl);
    cudaGetSymbolAddress((void**)&Vs, g_Vs);
    cudaGetSymbolAddress((void**)&KTh, g_KTh);   cudaGetSymbolAddress((void**)&KTl, g_KTl);
    cudaGetSymbolAddress((void**)&VTs, g_VTs);
    cudaGetSymbolAddress((void**)&G, g_G);       cudaGetSymbolAddress((void**)&s, g_s);
    cudaGetSymbolAddress((void**)&r, g_r);
    cudaGetSymbolAddress((void**)&Mh, g_Mh);     cudaGetSymbolAddress((void**)&Ml, g_Ml);
    cudaGetSymbolAddress((void**)&W2Ts, g_W2Ts);

    cudaFuncSetAttribute(gemm_hmma, cudaFuncAttributeMaxDynamicSharedMemorySize, GEMM_DSMEM);

    const long long nBS = (long long)BS * Dd;       // 16M
    const long long dd  = (long long)Dd * Dd;       // 1M
    const long long sd  = (long long)Sq * Dd;       // 4M

    // 0) input conversion
    split_conv_f16<<<(unsigned)((nBS + 255) / 256), 256>>>(x, xh, xl, nBS);
    transpose_conv_f16<<<dim3(Dd / 32, Dd / 32), dim3(32, 8)>>>(Wk, WkTs, Dd, Dd);
    transpose_conv_f16<<<dim3(Dd / 32, Dd / 32), dim3(32, 8)>>>(Wv, WvTs, Dd, Dd);
    conv_f16<<<(unsigned)((dd + 255) / 256), 256>>>(Wq, Wqs, dd);

    // 1) K = x@Wk + bk -> fp16 hi/lo ;  V = x@Wv + bv -> fp16 single
    gemm_hmma<<<dim3(Dd / 256, BS / 128, 1), 256, GEMM_DSMEM>>>(
        xh, xl, WkTs, bk, nullptr, Kh, Kl, Dd, Dd, 0, 0, 0, 0);
    gemm_hmma<<<dim3(Dd / 256, BS / 128, 1), 256, GEMM_DSMEM>>>(
        xh, xl, WvTs, bv, nullptr, Vs, nullptr, Dd, Dd, 0, 0, 0, 0);

    // 2) per-batch transpose: [Sq, D] -> [D, Sq]
    transpose_pair_f16<<<dim3(Dd / 64, Sq / 64, Bsz), 256>>>(Kh, Kl, KTh, KTl, Sq, Dd, sd, sd);
    transpose_f16<<<dim3(Dd / 64, Sq / 64, Bsz), 256>>>(Vs, VTs, Sq, Dd, sd, sd);

    // 3) G_b = K_b^T @ V_b  (M=N=1024, K=4096, batched)
    gemm_hmma<<<dim3(Dd / 256, Dd / 128, Bsz), 256, GEMM_DSMEM>>>(
        KTh, KTl, VTs, nullptr, G, nullptr, nullptr, Dd, Sq, sd, sd, 0, dd);

    // 4) s_b = circular anti-diagonal sum of G_b
    zero_s<<<Bsz * Dd / 256, 256>>>(s);
    reduce_s2<<<dim3(Dd / 256, 8, Bsz), 256>>>(G, s);

    // 5) M_b (fp16 hi/lo), r_b = bq @ M_b
    build_M_f16<<<dim3(Dd / 256, Dd, Bsz), 256>>>(s, Mh, Ml);
    compute_r<<<dim3(Dd / 256, Bsz), 256>>>(s, bq, r);

    // 6) W2T_b = M_b @ Wq^T -> fp16 single (M symmetric; B-side of stage 7)
    gemm_hmma<<<dim3(Dd / 256, Dd / 128, Bsz), 256, GEMM_DSMEM>>>(
        Mh, Ml, Wqs, nullptr, nullptr, W2Ts, nullptr, Dd, Dd, dd, 0, 0, dd);

    // 7) out_b = x_b @ W2_b + r_b  (fp32 out)
    gemm_hmma<<<dim3(Dd / 256, Sq / 128, Bsz), 256, GEMM_DSMEM>>>(
        xh, xl, W2Ts, r, out, nullptr, nullptr, Dd, Dd, sd, dd, Dd, sd);
}

// round 7
// speedup vs baseline: 1.8684x; 1.1885x over previous
#include <cuda_runtime.h>
#include <cuda_fp16.h>
#include <stdint.h>

#define Bsz 4
#define Sq  4096
#define Dd  1024
#define BS  (Bsz * Sq)   // 16384

// ---------------- scratch (device globals — allocation is forbidden) ----------------
__device__ __align__(256) __half g_xh[(long long)BS * Dd];
__device__ __align__(256) __half g_xl[(long long)BS * Dd];
__device__ __align__(256) __half g_WkTs[Dd * Dd];
__device__ __align__(256) __half g_WvTs[Dd * Dd];
__device__ __align__(256) __half g_Wqs[Dd * Dd];
__device__ __align__(256) float  g_Kf[(long long)BS * Dd];   // fp32 K
__device__ __align__(256) float  g_Vf[(long long)BS * Dd];   // fp32 V
__device__ __align__(256) float  g_S[Bsz * 513 * 2];         // accumulated bind spectrum
__device__ __align__(256) float  g_s[Bsz * Dd];
__device__ __align__(256) float  g_r[Bsz * Dd];
__device__ __align__(256) __half g_Mh[(long long)Bsz * Dd * Dd];
__device__ __align__(256) __half g_Ml[(long long)Bsz * Dd * Dd];
__device__ __align__(256) __half g_W2Ts[(long long)Bsz * Dd * Dd];

// ---------------- PTX helpers ----------------
__device__ __forceinline__ uint32_t smem_u32(const void* p) {
    uint32_t a;
    asm("{ .reg .u64 t; cvta.to.shared.u64 t, %1; cvt.u32.u64 %0, t; }" : "=r"(a) : "l"(p));
    return a;
}
__device__ __forceinline__ void cp16(uint32_t dst, const void* src) {
    asm volatile("cp.async.cg.shared.global [%0], [%1], 16;" :: "r"(dst), "l"(src));
}
__device__ __forceinline__ void cp_commit() { asm volatile("cp.async.commit_group;" ::: "memory"); }
__device__ __forceinline__ void cp_wait1()  { asm volatile("cp.async.wait_group 1;" ::: "memory"); }
__device__ __forceinline__ void cp_wait0()  { asm volatile("cp.async.wait_group 0;" ::: "memory"); }

__device__ __forceinline__ void ldsm_x4(uint32_t& r0, uint32_t& r1, uint32_t& r2, uint32_t& r3,
                                        uint32_t addr) {
    asm volatile("ldmatrix.sync.aligned.m8n8.x4.shared.b16 {%0,%1,%2,%3}, [%4];"
                 : "=r"(r0), "=r"(r1), "=r"(r2), "=r"(r3) : "r"(addr));
}
__device__ __forceinline__ void mma_fp16(float& c0, float& c1, float& c2, float& c3,
                                         uint32_t a0, uint32_t a1, uint32_t a2, uint32_t a3,
                                         uint32_t b0, uint32_t b1) {
    asm volatile(
        "mma.sync.aligned.m16n8k16.row.col.f32.f16.f16.f32 "
        "{%0,%1,%2,%3}, {%4,%5,%6,%7}, {%8,%9}, {%0,%1,%2,%3};"
        : "+f"(c0), "+f"(c1), "+f"(c2), "+f"(c3)
        : "r"(a0), "r"(a1), "r"(a2), "r"(a3), "r"(b0), "r"(b1));
}

// ---------------- 2-pass split-fp16 HMMA GEMM (identical core to R6) ----------------
#define A_BYTES 32768
#define B_BYTES 32768
#define STG     (A_BYTES + B_BYTES)
#define GEMM_DSMEM (2 * STG)

__global__ __launch_bounds__(256, 1) void gemm_hmma(
    const __half* __restrict__ Ah, const __half* __restrict__ Al,
    const __half* __restrict__ Bs,
    const float* __restrict__ bias, float* __restrict__ Cf,
    __half* __restrict__ Ch, __half* __restrict__ Cl,
    int N, int Ktot,
    long long sA, long long sB, long long sBias, long long sC)
{
    extern __shared__ __align__(128) char smem[];
    const int tid = threadIdx.x;
    const int wid = tid >> 5, lid = tid & 31;
    const int bz = blockIdx.z;
    const long long bm = (long long)blockIdx.y * 128;
    const long long bn = (long long)blockIdx.x * 256;

    const __half* gA[2] = { Ah + bz * sA + bm * Ktot, Al + bz * sA + bm * Ktot };
    const __half* gB = Bs + bz * sB + bn * Ktot;
    const float* biasp = bias ? bias + bz * sBias : nullptr;

    const uint32_t sb = smem_u32(smem);
    const int wm = (wid & 1) * 64;
    const int wn = (wid >> 1) * 64;

    float acc[4][8][4];
    #pragma unroll
    for (int a = 0; a < 4; a++)
        #pragma unroll
        for (int b = 0; b < 8; b++)
            #pragma unroll
            for (int c = 0; c < 4; c++) acc[a][b][c] = 0.f;

    auto load_chunk = [&](int p, int k0) {
        const uint32_t buf = sb + p * STG;
        #pragma unroll
        for (int it = 0; it < 8; it++) {
            int id = tid + it * 256;
            int pl = id >> 10, rem = id & 1023;
            int r = rem >> 3, c = rem & 7;
            cp16(buf + pl * 16384 + r * 128 + (((c ^ r) & 7) << 4),
                 gA[pl] + (long long)r * Ktot + k0 + c * 8);
        }
        #pragma unroll
        for (int it = 0; it < 8; it++) {
            int id = tid + it * 256;
            int r = id >> 3, c = id & 7;
            cp16(buf + A_BYTES + r * 128 + ((c ^ (r & 7)) << 4),
                 gB + (long long)r * Ktot + k0 + c * 8);
        }
        cp_commit();
    };

    const int nc = Ktot >> 6;
    load_chunk(0, 0);

    const int a_row = wm + (lid & 15);
    const int a_hi  = lid >> 4;
    const int b_row = wn + (lid & 7) + ((lid >> 4) & 1) * 8;
    const int b_hi  = (lid >> 3) & 1;

    for (int i = 0; i < nc; i++) {
        if (i + 1 < nc) { load_chunk((i + 1) & 1, (i + 1) << 6); cp_wait1(); }
        else            { cp_wait0(); }
        __syncthreads();

        const uint32_t buf = sb + (i & 1) * STG;
        #pragma unroll
        for (int kk = 0; kk < 4; kk++) {
            uint32_t Af[2][4][4];
            #pragma unroll
            for (int pl = 0; pl < 2; pl++)
                #pragma unroll
                for (int mb = 0; mb < 4; mb++) {
                    int r = a_row + mb * 16;
                    int c = kk * 2 + a_hi;
                    ldsm_x4(Af[pl][mb][0], Af[pl][mb][1], Af[pl][mb][2], Af[pl][mb][3],
                            buf + pl * 16384 + r * 128 + ((c ^ (r & 7)) << 4));
                }
            uint32_t Bf[4][4];
            #pragma unroll
            for (int nq = 0; nq < 4; nq++) {
                int r = b_row + nq * 16;
                int c = kk * 2 + b_hi;
                ldsm_x4(Bf[nq][0], Bf[nq][1], Bf[nq][2], Bf[nq][3],
                        buf + A_BYTES + r * 128 + ((c ^ (r & 7)) << 4));
            }
            #pragma unroll
            for (int mb = 0; mb < 4; mb++)
                #pragma unroll
                for (int nq = 0; nq < 4; nq++)
                    #pragma unroll
                    for (int half = 0; half < 2; half++) {
                        float* c = acc[mb][nq * 2 + half];
                        mma_fp16(c[0], c[1], c[2], c[3],
                                 Af[0][mb][0], Af[0][mb][1], Af[0][mb][2], Af[0][mb][3],
                                 Bf[nq][half * 2], Bf[nq][half * 2 + 1]);
                    }
            #pragma unroll
            for (int mb = 0; mb < 4; mb++)
                #pragma unroll
                for (int nq = 0; nq < 4; nq++)
                    #pragma unroll
                    for (int half = 0; half < 2; half++) {
                        float* c = acc[mb][nq * 2 + half];
                        mma_fp16(c[0], c[1], c[2], c[3],
                                 Af[1][mb][0], Af[1][mb][1], Af[1][mb][2], Af[1][mb][3],
                                 Bf[nq][half * 2], Bf[nq][half * 2 + 1]);
                    }
        }
        __syncthreads();
    }

    const int er = lid >> 2;
    const int ec = (lid & 3) * 2;
    #pragma unroll
    for (int mb = 0; mb < 4; mb++) {
        #pragma unroll
        for (int nb = 0; nb < 8; nb++) {
            const float* c = acc[mb][nb];
            long long col = bn + wn + nb * 8 + ec;
            float bx = 0.f, by = 0.f;
            if (biasp) { bx = biasp[col]; by = biasp[col + 1]; }
            long long r0 = bm + wm + mb * 16 + er;
            float v0 = c[0] + bx, v1 = c[1] + by;
            float v2 = c[2] + bx, v3 = c[3] + by;
            if (Cf) {
                float* Cb = Cf + bz * sC;
                *reinterpret_cast<float2*>(Cb + r0 * N + col) = make_float2(v0, v1);
                *reinterpret_cast<float2*>(Cb + (r0 + 8) * N + col) = make_float2(v2, v3);
            } else if (Cl) {
                __half h0 = __float2half(v0), h1 = __float2half(v1);
                __half h2 = __float2half(v2), h3 = __float2half(v3);
                __half2 hp0 = { h0, h1 }, hp1 = { h2, h3 };
                __half2 lp0 = { __float2half(v0 - __half2float(h0)),
                                __float2half(v1 - __half2float(h1)) };
                __half2 lp1 = { __float2half(v2 - __half2float(h2)),
                                __float2half(v3 - __half2float(h3)) };
                __half* Hb = Ch + bz * sC;
                __half* Lb = Cl + bz * sC;
                *reinterpret_cast<__half2*>(Hb + r0 * N + col) = hp0;
                *reinterpret_cast<__half2*>(Hb + (r0 + 8) * N + col) = hp1;
                *reinterpret_cast<__half2*>(Lb + r0 * N + col) = lp0;
                *reinterpret_cast<__half2*>(Lb + (r0 + 8) * N + col) = lp1;
            } else {
                __half2 s0 = { __float2half(v0), __float2half(v1) };
                __half2 s1 = { __float2half(v2), __float2half(v3) };
                __half* Hb = Ch + bz * sC;
                *reinterpret_cast<__half2*>(Hb + r0 * N + col) = s0;
                *reinterpret_cast<__half2*>(Hb + (r0 + 8) * N + col) = s1;
            }
        }
    }
}

// ---------------- FFT machinery (radix-4 Stockham, N=1024, 256 threads) ----------------
#define FPAD(i) ((i) + ((i) >> 5))     // bank-swizzle padding: 1024 -> 1056 slots

// 5 radix-4 stages. Input in (br0,bi0); OUTPUT lands in (br1,bi1).
// inv=0: forward (twiddle table must be exp(-2pi i t/1024));
// inv=1: inverse (table exp(+2pi i t/1024)); caller scales by 1/N.
__device__ __forceinline__ void fft1024_stages(
    float* br0, float* bi0, float* br1, float* bi1,
    const float* twr, const float* twi, int tid, int inv)
{
    float *sr = br0, *si = bi0, *dr = br1, *di = bi1;
    const int Ls[5] = {256, 64, 16, 4, 1};
    const int Ms[5] = {1, 4, 16, 64, 256};
    #pragma unroll
    for (int st = 0; st < 5; st++) {
        const int l = Ls[st], m = Ms[st];
        int j = tid / m, k = tid - j * m;
        int ti = j * (256 / l);
        float w1r = twr[ti], w1i = twi[ti];
        float w2r = w1r * w1r - w1i * w1i, w2i = 2.f * w1r * w1i;
        float w3r = w2r * w1r - w2i * w1i, w3i = w2r * w1i + w2i * w1r;
        int i0 = k + m * j;
        float c0r = sr[FPAD(i0)],             c0i = si[FPAD(i0)];
        float c1r = sr[FPAD(i0 + m * l)],     c1i = si[FPAD(i0 + m * l)];
        float c2r = sr[FPAD(i0 + 2 * m * l)], c2i = si[FPAD(i0 + 2 * m * l)];
        float c3r = sr[FPAD(i0 + 3 * m * l)], c3i = si[FPAD(i0 + 3 * m * l)];
        float t0r = c0r + c2r, t0i = c0i + c2i;
        float t1r = c0r - c2r, t1i = c0i - c2i;
        float t2r = c1r + c3r, t2i = c1i + c3i;
        float t3r = c1r - c3r, t3i = c1i - c3i;
        float u0r = t0r + t2r, u0i = t0i + t2i;
        float u2r = t0r - t2r, u2i = t0i - t2i;
        float u1r, u1i, u3r, u3i;
        if (!inv) { u1r = t1r + t3i; u1i = t1i - t3r; u3r = t1r - t3i; u3i = t1i + t3r; }
        else      { u1r = t1r - t3i; u1i = t1i + t3r; u3r = t1r + t3i; u3i = t1i - t3r; }
        int o = k + 4 * m * j;
        dr[FPAD(o)]         = u0r;                    di[FPAD(o)]         = u0i;
        dr[FPAD(o + m)]     = w1r * u1r - w1i * u1i;  di[FPAD(o + m)]     = w1r * u1i + w1i * u1r;
        dr[FPAD(o + 2 * m)] = w2r * u2r - w2i * u2i;  di[FPAD(o + 2 * m)] = w2r * u2i + w2i * u2r;
        dr[FPAD(o + 3 * m)] = w3r * u3r - w3i * u3i;  di[FPAD(o + 3 * m)] = w3r * u3i + w3i * u3r;
        __syncthreads();
        float* t;
        t = sr; sr = dr; dr = t;
        t = si; si = di; di = t;
    }
}

#define TOKC 32   // tokens per CTA

// s-spectrum accumulate: for each token, Z = FFT(k + i*v); P[f] = Khat*Vhat; atomically sum.
__global__ __launch_bounds__(256) void bind_fft(
    const float* __restrict__ Kf, const float* __restrict__ Vf, float* __restrict__ Sacc)
{
    __shared__ float Ar0[1056], Ai0[1056], Ar1[1056], Ai1[1056];
    __shared__ float twr[256], twi[256];
    const int tid = threadIdx.x;
    const int b = blockIdx.y;
    const long long base = ((long long)b * Sq + (long long)blockIdx.x * TOKC) * Dd;

    {   // forward twiddles exp(-2pi i t/1024)
        float sv, cv;
        __sincosf(-6.28318530717958647692f * (float)tid / 1024.f, &sv, &cv);
        twr[tid] = cv; twi[tid] = sv;
    }
    float aR0 = 0.f, aI0 = 0.f, aR1 = 0.f, aI1 = 0.f, aR2 = 0.f, aI2 = 0.f;

    for (int tok = 0; tok < TOKC; tok++) {
        const float* kr = Kf + base + (long long)tok * Dd;
        const float* vr = Vf + base + (long long)tok * Dd;
        __syncthreads();                    // prior extraction reads done
        #pragma unroll
        for (int q = 0; q < 4; q++) {
            int i = tid + 256 * q;
            Ar0[FPAD(i)] = kr[i];
            Ai0[FPAD(i)] = vr[i];
        }
        __syncthreads();
        fft1024_stages(Ar0, Ai0, Ar1, Ai1, twr, twi, tid, 0);   // out in Ar1/Ai1

        // extraction: thread owns f = tid and f = tid+256; thread 0 also f = 512
        #pragma unroll
        for (int h = 0; h < 2; h++) {
            int f = tid + h * 256;
            int nf = (1024 - f) & 1023;
            float Zr = Ar1[FPAD(f)],  Zi = Ai1[FPAD(f)];
            float Br = Ar1[FPAD(nf)], Bi = Ai1[FPAD(nf)];
            float Kr_ = 0.5f * (Zr + Br), Ki_ = 0.5f * (Zi - Bi);
            float Vr_ = 0.5f * (Zi + Bi), Vi_ = 0.5f * (Br - Zr);
            float Pr = Kr_ * Vr_ - Ki_ * Vi_;
            float Pi = Kr_ * Vi_ + Ki_ * Vr_;
            if (h == 0) { aR0 += Pr; aI0 += Pi; }
            else        { aR1 += Pr; aI1 += Pi; }
        }
        if (tid == 0) {
            float Zr = Ar1[FPAD(512)], Zi = Ai1[FPAD(512)];
            // nf == 512: Khat = Re(Z), Vhat = Im(Z) (both real)
            aR2 += Zr * Zi;   // P = Khat*Vhat, purely real
        }
    }
    float* Sb = Sacc + b * 513 * 2;
    atomicAdd(&Sb[tid * 2 + 0], aR0);
    atomicAdd(&Sb[tid * 2 + 1], aI0);
    atomicAdd(&Sb[(tid + 256) * 2 + 0], aR1);
    atomicAdd(&Sb[(tid + 256) * 2 + 1], aI1);
    if (tid == 0) { atomicAdd(&Sb[512 * 2 + 0], aR2); atomicAdd(&Sb[512 * 2 + 1], aI2); }
}

// irfft of the accumulated spectrum -> s_b[1024]; one CTA per batch
__global__ __launch_bounds__(256) void irfft_s(const float* __restrict__ Sacc,
                                               float* __restrict__ s)
{
    __shared__ float Ar0[1056], Ai0[1056], Ar1[1056], Ai1[1056];
    __shared__ float twr[256], twi[256];
    const int tid = threadIdx.x;
    const int b = blockIdx.x;
    const float* Sb = Sacc + b * 513 * 2;
    {   // inverse twiddles exp(+2pi i t/1024)
        float sv, cv;
        __sincosf(6.28318530717958647692f * (float)tid / 1024.f, &sv, &cv);
        twr[tid] = cv; twi[tid] = sv;
    }
    #pragma unroll
    for (int q = 0; q < 4; q++) {
        int i = tid + 256 * q;
        float re, im;
        if (i <= 512) { re = Sb[i * 2]; im = Sb[i * 2 + 1]; }
        else          { re = Sb[(1024 - i) * 2]; im = -Sb[(1024 - i) * 2 + 1]; }
        Ar0[FPAD(i)] = re;
        Ai0[FPAD(i)] = im;
    }
    __syncthreads();
    fft1024_stages(Ar0, Ai0, Ar1, Ai1, twr, twi, tid, 1);
    #pragma unroll
    for (int q = 0; q < 4; q++) {
        int i = tid + 256 * q;
        s[b * Dd + i] = Ar1[FPAD(i)] * (1.f / 1024.f);
    }
}

// ---------------- prep kernels ----------------
__global__ void zero_S(float* p, int n)
{
    int i = blockIdx.x * 256 + threadIdx.x;
    if (i < n) p[i] = 0.f;
}

// vectorized split: 4 floats/thread
__global__ void split_conv_f16v(const float4* __restrict__ x, __half2* __restrict__ h,
                                __half2* __restrict__ l, long long n4)
{
    long long i = (long long)blockIdx.x * blockDim.x + threadIdx.x;
    if (i < n4) {
        float4 v = x[i];
        __half h0 = __float2half(v.x), h1 = __float2half(v.y);
        __half h2 = __float2half(v.z), h3 = __float2half(v.w);
        h[i * 2 + 0] = __half2{h0, h1};
        h[i * 2 + 1] = __half2{h2, h3};
        l[i * 2 + 0] = __half2{__float2half(v.x - __half2float(h0)),
                               __float2half(v.y - __half2float(h1))};
        l[i * 2 + 1] = __half2{__float2half(v.z - __half2float(h2)),
                               __float2half(v.w - __half2float(h3))};
    }
}

__global__ void conv_f16(const float* __restrict__ s, __half* __restrict__ d, long long n)
{
    long long i = (long long)blockIdx.x * blockDim.x + threadIdx.x;
    if (i < n) d[i] = __float2half(s[i]);
}

__global__ void transpose_conv_f16(const float* __restrict__ src, __half* __restrict__ dst,
                                   int R, int C)
{
    __shared__ float t[32][33];
    int c0 = blockIdx.x * 32, r0 = blockIdx.y * 32;
    int tx = threadIdx.x, ty = threadIdx.y;
    #pragma unroll
    for (int k = 0; k < 32; k += 8)
        t[ty + k][tx] = src[(long long)(r0 + ty + k) * C + c0 + tx];
    __syncthreads();
    #pragma unroll
    for (int k = 0; k < 32; k += 8)
        dst[(long long)(c0 + ty + k) * R + r0 + tx] = __float2half(t[tx][ty + k]);
}

__global__ void build_M_f16(const float* __restrict__ s,
                            __half* __restrict__ h, __half* __restrict__ l)
{
    int b = blockIdx.z, k = blockIdx.y;
    int n = blockIdx.x * 256 + threadIdx.x;
    float v = s[b * Dd + ((k + n) & (Dd - 1))];
    __half hi = __float2half(v);
    long long o = ((long long)b << 20) + ((long long)k << 10) + n;
    h[o] = hi;
    l[o] = __float2half(v - __half2float(hi));
}

__global__ void compute_r(const float* __restrict__ s, const float* __restrict__ bq,
                          float* __restrict__ r)
{
    int b = blockIdx.y;
    int n = blockIdx.x * 256 + threadIdx.x;
    float acc = 0.f;
    for (int m = 0; m < Dd; m++)
        acc += bq[m] * s[b * Dd + ((m + n) & (Dd - 1))];
    r[b * Dd + n] = acc;
}

// ---------------- launcher ----------------
extern "C" void kernel_launch(void* const* d_in, const int* in_sizes, int n_in,
                              void* d_out, int out_size)
{
    const float* x  = (const float*)d_in[0];
    const float* Wq = (const float*)d_in[1];
    const float* bq = (const float*)d_in[2];
    const float* Wk = (const float*)d_in[3];
    const float* bk = (const float*)d_in[4];
    const float* Wv = (const float*)d_in[5];
    const float* bv = (const float*)d_in[6];
    float* out = (float*)d_out;

    __half *xh, *xl, *WkTs, *WvTs, *Wqs, *Mh, *Ml, *W2Ts;
    float *Kf, *Vf, *S, *s, *r;
    cudaGetSymbolAddress((void**)&xh, g_xh);     cudaGetSymbolAddress((void**)&xl, g_xl);
    cudaGetSymbolAddress((void**)&WkTs, g_WkTs); cudaGetSymbolAddress((void**)&WvTs, g_WvTs);
    cudaGetSymbolAddress((void**)&Wqs, g_Wqs);
    cudaGetSymbolAddress((void**)&Kf, g_Kf);     cudaGetSymbolAddress((void**)&Vf, g_Vf);
    cudaGetSymbolAddress((void**)&S, g_S);
    cudaGetSymbolAddress((void**)&s, g_s);       cudaGetSymbolAddress((void**)&r, g_r);
    cudaGetSymbolAddress((void**)&Mh, g_Mh);     cudaGetSymbolAddress((void**)&Ml, g_Ml);
    cudaGetSymbolAddress((void**)&W2Ts, g_W2Ts);

    cudaFuncSetAttribute(gemm_hmma, cudaFuncAttributeMaxDynamicSharedMemorySize, GEMM_DSMEM);

    const long long nBS = (long long)BS * Dd;       // 16M
    const long long dd  = (long long)Dd * Dd;       // 1M
    const long long sd  = (long long)Sq * Dd;       // 4M

    // 0) input conversion
    split_conv_f16v<<<(unsigned)(nBS / 4 / 256), 256>>>(
        (const float4*)x, (__half2*)xh, (__half2*)xl, nBS / 4);
    transpose_conv_f16<<<dim3(Dd / 32, Dd / 32), dim3(32, 8)>>>(Wk, WkTs, Dd, Dd);
    transpose_conv_f16<<<dim3(Dd / 32, Dd / 32), dim3(32, 8)>>>(Wv, WvTs, Dd, Dd);
    conv_f16<<<(unsigned)((dd + 255) / 256), 256>>>(Wq, Wqs, dd);

    // 1) K = x@Wk + bk ; V = x@Wv + bv  -> fp32 [BS, D]
    gemm_hmma<<<dim3(Dd / 256, BS / 128, 1), 256, GEMM_DSMEM>>>(
        xh, xl, WkTs, bk, Kf, nullptr, nullptr, Dd, Dd, 0, 0, 0, 0);
    gemm_hmma<<<dim3(Dd / 256, BS / 128, 1), 256, GEMM_DSMEM>>>(
        xh, xl, WvTs, bv, Vf, nullptr, nullptr, Dd, Dd, 0, 0, 0, 0);

    // 2) s_b = irfft( sum_t rfft(k_t) * rfft(v_t) )  — FFT bind-sum
    zero_S<<<(Bsz * 513 * 2 + 255) / 256, 256>>>(S, Bsz * 513 * 2);
    bind_fft<<<dim3(Sq / TOKC, Bsz), 256>>>(Kf, Vf, S);
    irfft_s<<<Bsz, 256>>>(S, s);

    // 3) M_b (fp16 hi/lo), r_b = bq @ M_b
    build_M_f16<<<dim3(Dd / 256, Dd, Bsz), 256>>>(s, Mh, Ml);
    compute_r<<<dim3(Dd / 256, Bsz), 256>>>(s, bq, r);

    // 4) W2T_b = M_b @ Wq^T -> fp16 single (M symmetric)
    gemm_hmma<<<dim3(Dd / 256, Dd / 128, Bsz), 256, GEMM_DSMEM>>>(
        Mh, Ml, Wqs, nullptr, nullptr, W2Ts, nullptr, Dd, Dd, dd, 0, 0, dd);

    // 5) out_b = x_b @ W2_b + r_b  (fp32 out)
    gemm_hmma<<<dim3(Dd / 256, Sq / 128, Bsz), 256, GEMM_DSMEM>>>(
        xh, xl, W2Ts, r, out, nullptr, nullptr, Dd, Dd, sd, dd, Dd, sd);
}

// round 8
// speedup vs baseline: 2.6443x; 1.4153x over previous
#include <cuda_runtime.h>
#include <cuda_fp16.h>
#include <stdint.h>

#define Bsz 4
#define Sq  4096
#define Dd  1024
#define BS  (Bsz * Sq)   // 16384

// ---------------- scratch (device globals — allocation is forbidden) ----------------
__device__ __align__(256) __half g_xh[(long long)BS * Dd];
__device__ __align__(256) __half g_WkTs[Dd * Dd];
__device__ __align__(256) __half g_WvTs[Dd * Dd];
__device__ __align__(256) __half g_Wqs[Dd * Dd];
__device__ __align__(256) float  g_Kf[(long long)BS * Dd];
__device__ __align__(256) float  g_Vf[(long long)BS * Dd];
__device__ __align__(256) float  g_S[Bsz * 513 * 2];
__device__ __align__(256) float  g_s[Bsz * Dd];
__device__ __align__(256) float  g_r[Bsz * Dd];
__device__ __align__(256) __half g_Mh[(long long)Bsz * Dd * Dd];
__device__ __align__(256) __half g_Ml[(long long)Bsz * Dd * Dd];
__device__ __align__(256) __half g_W2Ts[(long long)Bsz * Dd * Dd];

// ---------------- PTX helpers ----------------
__device__ __forceinline__ uint32_t smem_u32(const void* p) {
    uint32_t a;
    asm("{ .reg .u64 t; cvta.to.shared.u64 t, %1; cvt.u32.u64 %0, t; }" : "=r"(a) : "l"(p));
    return a;
}
__device__ __forceinline__ void cp16(uint32_t dst, const void* src) {
    asm volatile("cp.async.cg.shared.global [%0], [%1], 16;" :: "r"(dst), "l"(src));
}
__device__ __forceinline__ void cp_commit() { asm volatile("cp.async.commit_group;" ::: "memory"); }
__device__ __forceinline__ void cp_wait1()  { asm volatile("cp.async.wait_group 1;" ::: "memory"); }
__device__ __forceinline__ void cp_wait0()  { asm volatile("cp.async.wait_group 0;" ::: "memory"); }

__device__ __forceinline__ void ldsm_x4(uint32_t& r0, uint32_t& r1, uint32_t& r2, uint32_t& r3,
                                        uint32_t addr) {
    asm volatile("ldmatrix.sync.aligned.m8n8.x4.shared.b16 {%0,%1,%2,%3}, [%4];"
                 : "=r"(r0), "=r"(r1), "=r"(r2), "=r"(r3) : "r"(addr));
}
__device__ __forceinline__ void mma_fp16(float& c0, float& c1, float& c2, float& c3,
                                         uint32_t a0, uint32_t a1, uint32_t a2, uint32_t a3,
                                         uint32_t b0, uint32_t b1) {
    asm volatile(
        "mma.sync.aligned.m16n8k16.row.col.f32.f16.f16.f32 "
        "{%0,%1,%2,%3}, {%4,%5,%6,%7}, {%8,%9}, {%0,%1,%2,%3};"
        : "+f"(c0), "+f"(c1), "+f"(c2), "+f"(c3)
        : "r"(a0), "r"(a1), "r"(a2), "r"(a3), "r"(b0), "r"(b1));
}

// ---------------- fp16 HMMA GEMM: C[M,N] = (Ah [+Al]) @ Bs^T (+bias[n]) ----------------
// Al == nullptr -> single-pass.  Output: Cf fp32 | (Ch,Cl) hi/lo | Ch single fp16.
// CTA tile 128(M) x 256(N) x 64(K), 8 warps (2 M x 4 N), warp tile 64x64.
// SMEM row = 128B; 16B chunk c at slot c ^ (row & 7): conflict-free.
#define A_BYTES 32768
#define B_BYTES 32768
#define STG     (A_BYTES + B_BYTES)
#define GEMM_DSMEM (2 * STG)

__global__ __launch_bounds__(256, 1) void gemm_hmma(
    const __half* __restrict__ Ah, const __half* __restrict__ Al,
    const __half* __restrict__ Bs,
    const float* __restrict__ bias, float* __restrict__ Cf,
    __half* __restrict__ Ch, __half* __restrict__ Cl,
    int N, int Ktot,
    long long sA, long long sB, long long sBias, long long sC)
{
    extern __shared__ __align__(128) char smem[];
    const int tid = threadIdx.x;
    const int wid = tid >> 5, lid = tid & 31;
    const int bz = blockIdx.z;
    const long long bm = (long long)blockIdx.y * 128;
    const long long bn = (long long)blockIdx.x * 256;

    const __half* gA0 = Ah + bz * sA + bm * Ktot;
    const __half* gA1 = Al ? Al + bz * sA + bm * Ktot : nullptr;
    const __half* gB = Bs + bz * sB + bn * Ktot;
    const float* biasp = bias ? bias + bz * sBias : nullptr;

    const uint32_t sb = smem_u32(smem);
    const int wm = (wid & 1) * 64;
    const int wn = (wid >> 1) * 64;

    float acc[4][8][4];
    #pragma unroll
    for (int a = 0; a < 4; a++)
        #pragma unroll
        for (int b = 0; b < 8; b++)
            #pragma unroll
            for (int c = 0; c < 4; c++) acc[a][b][c] = 0.f;

    auto load_chunk = [&](int p, int k0) {
        const uint32_t buf = sb + p * STG;
        // A plane 0: 128 rows x 8 chunks = 1024 -> 4 iters
        #pragma unroll
        for (int it = 0; it < 4; it++) {
            int id = tid + it * 256;
            int r = id >> 3, c = id & 7;
            cp16(buf + r * 128 + (((c ^ r) & 7) << 4),
                 gA0 + (long long)r * Ktot + k0 + c * 8);
        }
        if (gA1) {
            #pragma unroll
            for (int it = 0; it < 4; it++) {
                int id = tid + it * 256;
                int r = id >> 3, c = id & 7;
                cp16(buf + 16384 + r * 128 + (((c ^ r) & 7) << 4),
                     gA1 + (long long)r * Ktot + k0 + c * 8);
            }
        }
        // B: 256 rows x 8 chunks = 2048 -> 8 iters
        #pragma unroll
        for (int it = 0; it < 8; it++) {
            int id = tid + it * 256;
            int r = id >> 3, c = id & 7;
            cp16(buf + A_BYTES + r * 128 + ((c ^ (r & 7)) << 4),
                 gB + (long long)r * Ktot + k0 + c * 8);
        }
        cp_commit();
    };

    const int nc = Ktot >> 6;
    load_chunk(0, 0);

    const int a_row = wm + (lid & 15);
    const int a_hi  = lid >> 4;
    const int b_row = wn + (lid & 7) + ((lid >> 4) & 1) * 8;
    const int b_hi  = (lid >> 3) & 1;

    for (int i = 0; i < nc; i++) {
        if (i + 1 < nc) { load_chunk((i + 1) & 1, (i + 1) << 6); cp_wait1(); }
        else            { cp_wait0(); }
        __syncthreads();

        const uint32_t buf = sb + (i & 1) * STG;
        #pragma unroll
        for (int kk = 0; kk < 4; kk++) {
            uint32_t Af0[4][4];
            #pragma unroll
            for (int mb = 0; mb < 4; mb++) {
                int r = a_row + mb * 16;
                int c = kk * 2 + a_hi;
                ldsm_x4(Af0[mb][0], Af0[mb][1], Af0[mb][2], Af0[mb][3],
                        buf + r * 128 + ((c ^ (r & 7)) << 4));
            }
            uint32_t Bf[4][4];
            #pragma unroll
            for (int nq = 0; nq < 4; nq++) {
                int r = b_row + nq * 16;
                int c = kk * 2 + b_hi;
                ldsm_x4(Bf[nq][0], Bf[nq][1], Bf[nq][2], Bf[nq][3],
                        buf + A_BYTES + r * 128 + ((c ^ (r & 7)) << 4));
            }
            #pragma unroll
            for (int mb = 0; mb < 4; mb++)
                #pragma unroll
                for (int nq = 0; nq < 4; nq++)
                    #pragma unroll
                    for (int half = 0; half < 2; half++) {
                        float* c = acc[mb][nq * 2 + half];
                        mma_fp16(c[0], c[1], c[2], c[3],
                                 Af0[mb][0], Af0[mb][1], Af0[mb][2], Af0[mb][3],
                                 Bf[nq][half * 2], Bf[nq][half * 2 + 1]);
                    }
            if (gA1) {
                uint32_t Af1[4][4];
                #pragma unroll
                for (int mb = 0; mb < 4; mb++) {
                    int r = a_row + mb * 16;
                    int c = kk * 2 + a_hi;
                    ldsm_x4(Af1[mb][0], Af1[mb][1], Af1[mb][2], Af1[mb][3],
                            buf + 16384 + r * 128 + ((c ^ (r & 7)) << 4));
                }
                #pragma unroll
                for (int mb = 0; mb < 4; mb++)
                    #pragma unroll
                    for (int nq = 0; nq < 4; nq++)
                        #pragma unroll
                        for (int half = 0; half < 2; half++) {
                            float* c = acc[mb][nq * 2 + half];
                            mma_fp16(c[0], c[1], c[2], c[3],
                                     Af1[mb][0], Af1[mb][1], Af1[mb][2], Af1[mb][3],
                                     Bf[nq][half * 2], Bf[nq][half * 2 + 1]);
                        }
            }
        }
        __syncthreads();
    }

    const int er = lid >> 2;
    const int ec = (lid & 3) * 2;
    #pragma unroll
    for (int mb = 0; mb < 4; mb++) {
        #pragma unroll
        for (int nb = 0; nb < 8; nb++) {
            const float* c = acc[mb][nb];
            long long col = bn + wn + nb * 8 + ec;
            float bx = 0.f, by = 0.f;
            if (biasp) { bx = biasp[col]; by = biasp[col + 1]; }
            long long r0 = bm + wm + mb * 16 + er;
            float v0 = c[0] + bx, v1 = c[1] + by;
            float v2 = c[2] + bx, v3 = c[3] + by;
            if (Cf) {
                float* Cb = Cf + bz * sC;
                *reinterpret_cast<float2*>(Cb + r0 * N + col) = make_float2(v0, v1);
                *reinterpret_cast<float2*>(Cb + (r0 + 8) * N + col) = make_float2(v2, v3);
            } else if (Cl) {
                __half h0 = __float2half(v0), h1 = __float2half(v1);
                __half h2 = __float2half(v2), h3 = __float2half(v3);
                __half2 hp0 = { h0, h1 }, hp1 = { h2, h3 };
                __half2 lp0 = { __float2half(v0 - __half2float(h0)),
                                __float2half(v1 - __half2float(h1)) };
                __half2 lp1 = { __float2half(v2 - __half2float(h2)),
                                __float2half(v3 - __half2float(h3)) };
                __half* Hb = Ch + bz * sC;
                __half* Lb = Cl + bz * sC;
                *reinterpret_cast<__half2*>(Hb + r0 * N + col) = hp0;
                *reinterpret_cast<__half2*>(Hb + (r0 + 8) * N + col) = hp1;
                *reinterpret_cast<__half2*>(Lb + r0 * N + col) = lp0;
                *reinterpret_cast<__half2*>(Lb + (r0 + 8) * N + col) = lp1;
            } else {
                __half2 s0 = { __float2half(v0), __float2half(v1) };
                __half2 s1 = { __float2half(v2), __float2half(v3) };
                __half* Hb = Ch + bz * sC;
                *reinterpret_cast<__half2*>(Hb + r0 * N + col) = s0;
                *reinterpret_cast<__half2*>(Hb + (r0 + 8) * N + col) = s1;
            }
        }
    }
}

// ---------------- FFT machinery (radix-4 Stockham, N=1024, 256 threads) ----------------
#define FPAD(i) ((i) + ((i) >> 5))

__device__ __forceinline__ void fft1024_stages(
    float* br0, float* bi0, float* br1, float* bi1,
    const float* twr, const float* twi, int tid, int inv)
{
    float *sr = br0, *si = bi0, *dr = br1, *di = bi1;
    const int Ls[5] = {256, 64, 16, 4, 1};
    const int Ms[5] = {1, 4, 16, 64, 256};
    #pragma unroll
    for (int st = 0; st < 5; st++) {
        const int l = Ls[st], m = Ms[st];
        int j = tid / m, k = tid - j * m;
        int ti = j * (256 / l);
        float w1r = twr[ti], w1i = twi[ti];
        float w2r = w1r * w1r - w1i * w1i, w2i = 2.f * w1r * w1i;
        float w3r = w2r * w1r - w2i * w1i, w3i = w2r * w1i + w2i * w1r;
        int i0 = k + m * j;
        float c0r = sr[FPAD(i0)],             c0i = si[FPAD(i0)];
        float c1r = sr[FPAD(i0 + m * l)],     c1i = si[FPAD(i0 + m * l)];
        float c2r = sr[FPAD(i0 + 2 * m * l)], c2i = si[FPAD(i0 + 2 * m * l)];
        float c3r = sr[FPAD(i0 + 3 * m * l)], c3i = si[FPAD(i0 + 3 * m * l)];
        float t0r = c0r + c2r, t0i = c0i + c2i;
        float t1r = c0r - c2r, t1i = c0i - c2i;
        float t2r = c1r + c3r, t2i = c1i + c3i;
        float t3r = c1r - c3r, t3i = c1i - c3i;
        float u0r = t0r + t2r, u0i = t0i + t2i;
        float u2r = t0r - t2r, u2i = t0i - t2i;
        float u1r, u1i, u3r, u3i;
        if (!inv) { u1r = t1r + t3i; u1i = t1i - t3r; u3r = t1r - t3i; u3i = t1i + t3r; }
        else      { u1r = t1r - t3i; u1i = t1i + t3r; u3r = t1r + t3i; u3i = t1i - t3r; }
        int o = k + 4 * m * j;
        dr[FPAD(o)]         = u0r;                    di[FPAD(o)]         = u0i;
        dr[FPAD(o + m)]     = w1r * u1r - w1i * u1i;  di[FPAD(o + m)]     = w1r * u1i + w1i * u1r;
        dr[FPAD(o + 2 * m)] = w2r * u2r - w2i * u2i;  di[FPAD(o + 2 * m)] = w2r * u2i + w2i * u2r;
        dr[FPAD(o + 3 * m)] = w3r * u3r - w3i * u3i;  di[FPAD(o + 3 * m)] = w3r * u3i + w3i * u3r;
        __syncthreads();
        float* t;
        t = sr; sr = dr; dr = t;
        t = si; si = di; di = t;
    }
}

#define TOKC 32

__global__ __launch_bounds__(256) void bind_fft(
    const float* __restrict__ Kf, const float* __restrict__ Vf, float* __restrict__ Sacc)
{
    __shared__ float Ar0[1056], Ai0[1056], Ar1[1056], Ai1[1056];
    __shared__ float twr[256], twi[256];
    const int tid = threadIdx.x;
    const int b = blockIdx.y;
    const long long base = ((long long)b * Sq + (long long)blockIdx.x * TOKC) * Dd;

    {
        float sv, cv;
        __sincosf(-6.28318530717958647692f * (float)tid / 1024.f, &sv, &cv);
        twr[tid] = cv; twi[tid] = sv;
    }
    float aR0 = 0.f, aI0 = 0.f, aR1 = 0.f, aI1 = 0.f, aR2 = 0.f;

    for (int tok = 0; tok < TOKC; tok++) {
        const float* kr = Kf + base + (long long)tok * Dd;
        const float* vr = Vf + base + (long long)tok * Dd;
        __syncthreads();
        #pragma unroll
        for (int q = 0; q < 4; q++) {
            int i = tid + 256 * q;
            Ar0[FPAD(i)] = kr[i];
            Ai0[FPAD(i)] = vr[i];
        }
        __syncthreads();
        fft1024_stages(Ar0, Ai0, Ar1, Ai1, twr, twi, tid, 0);

        #pragma unroll
        for (int h = 0; h < 2; h++) {
            int f = tid + h * 256;
            int nf = (1024 - f) & 1023;
            float Zr = Ar1[FPAD(f)],  Zi = Ai1[FPAD(f)];
            float Br = Ar1[FPAD(nf)], Bi = Ai1[FPAD(nf)];
            float Kr_ = 0.5f * (Zr + Br), Ki_ = 0.5f * (Zi - Bi);
            float Vr_ = 0.5f * (Zi + Bi), Vi_ = 0.5f * (Br - Zr);
            float Pr = Kr_ * Vr_ - Ki_ * Vi_;
            float Pi = Kr_ * Vi_ + Ki_ * Vr_;
            if (h == 0) { aR0 += Pr; aI0 += Pi; }
            else        { aR1 += Pr; aI1 += Pi; }
        }
        if (tid == 0) {
            float Zr = Ar1[FPAD(512)], Zi = Ai1[FPAD(512)];
            aR2 += Zr * Zi;
        }
    }
    float* Sb = Sacc + b * 513 * 2;
    atomicAdd(&Sb[tid * 2 + 0], aR0);
    atomicAdd(&Sb[tid * 2 + 1], aI0);
    atomicAdd(&Sb[(tid + 256) * 2 + 0], aR1);
    atomicAdd(&Sb[(tid + 256) * 2 + 1], aI1);
    if (tid == 0) atomicAdd(&Sb[512 * 2 + 0], aR2);
}

__global__ __launch_bounds__(256) void irfft_s(const float* __restrict__ Sacc,
                                               float* __restrict__ s)
{
    __shared__ float Ar0[1056], Ai0[1056], Ar1[1056], Ai1[1056];
    __shared__ float twr[256], twi[256];
    const int tid = threadIdx.x;
    const int b = blockIdx.x;
    const float* Sb = Sacc + b * 513 * 2;
    {
        float sv, cv;
        __sincosf(6.28318530717958647692f * (float)tid / 1024.f, &sv, &cv);
        twr[tid] = cv; twi[tid] = sv;
    }
    #pragma unroll
    for (int q = 0; q < 4; q++) {
        int i = tid + 256 * q;
        float re, im;
        if (i <= 512) { re = Sb[i * 2]; im = Sb[i * 2 + 1]; }
        else          { re = Sb[(1024 - i) * 2]; im = -Sb[(1024 - i) * 2 + 1]; }
        Ar0[FPAD(i)] = re;
        Ai0[FPAD(i)] = im;
    }
    __syncthreads();
    fft1024_stages(Ar0, Ai0, Ar1, Ai1, twr, twi, tid, 1);
    #pragma unroll
    for (int q = 0; q < 4; q++) {
        int i = tid + 256 * q;
        s[b * Dd + i] = Ar1[FPAD(i)] * (1.f / 1024.f);
    }
}

// ---------------- prep kernels ----------------
__global__ void zero_S(float* p, int n)
{
    int i = blockIdx.x * 256 + threadIdx.x;
    if (i < n) p[i] = 0.f;
}

__global__ void conv_f16v(const float4* __restrict__ x, __half2* __restrict__ h, long long n4)
{
    long long i = (long long)blockIdx.x * blockDim.x + threadIdx.x;
    if (i < n4) {
        float4 v = x[i];
        h[i * 2 + 0] = __half2{__float2half(v.x), __float2half(v.y)};
        h[i * 2 + 1] = __half2{__float2half(v.z), __float2half(v.w)};
    }
}

__global__ void conv_f16(const float* __restrict__ s, __half* __restrict__ d, long long n)
{
    long long i = (long long)blockIdx.x * blockDim.x + threadIdx.x;
    if (i < n) d[i] = __float2half(s[i]);
}

__global__ void transpose_conv_f16(const float* __restrict__ src, __half* __restrict__ dst,
                                   int R, int C)
{
    __shared__ float t[32][33];
    int c0 = blockIdx.x * 32, r0 = blockIdx.y * 32;
    int tx = threadIdx.x, ty = threadIdx.y;
    #pragma unroll
    for (int k = 0; k < 32; k += 8)
        t[ty + k][tx] = src[(long long)(r0 + ty + k) * C + c0 + tx];
    __syncthreads();
    #pragma unroll
    for (int k = 0; k < 32; k += 8)
        dst[(long long)(c0 + ty + k) * R + r0 + tx] = __float2half(t[tx][ty + k]);
}

__global__ void build_M_f16(const float* __restrict__ s,
                            __half* __restrict__ h, __half* __restrict__ l)
{
    int b = blockIdx.z, k = blockIdx.y;
    int n = blockIdx.x * 256 + threadIdx.x;
    float v = s[b * Dd + ((k + n) & (Dd - 1))];
    __half hi = __float2half(v);
    long long o = ((long long)b << 20) + ((long long)k << 10) + n;
    h[o] = hi;
    l[o] = __float2half(v - __half2float(hi));
}

__global__ void compute_r(const float* __restrict__ s, const float* __restrict__ bq,
                          float* __restrict__ r)
{
    int b = blockIdx.y;
    int n = blockIdx.x * 256 + threadIdx.x;
    float acc = 0.f;
    for (int m = 0; m < Dd; m++)
        acc += bq[m] * s[b * Dd + ((m + n) & (Dd - 1))];
    r[b * Dd + n] = acc;
}

// ---------------- launcher ----------------
extern "C" void kernel_launch(void* const* d_in, const int* in_sizes, int n_in,
                              void* d_out, int out_size)
{
    const float* x  = (const float*)d_in[0];
    const float* Wq = (const float*)d_in[1];
    const float* bq = (const float*)d_in[2];
    const float* Wk = (const float*)d_in[3];
    const float* bk = (const float*)d_in[4];
    const float* Wv = (const float*)d_in[5];
    const float* bv = (const float*)d_in[6];
    float* out = (float*)d_out;

    __half *xh, *WkTs, *WvTs, *Wqs, *Mh, *Ml, *W2Ts;
    float *Kf, *Vf, *S, *s, *r;
    cudaGetSymbolAddress((void**)&xh, g_xh);
    cudaGetSymbolAddress((void**)&WkTs, g_WkTs); cudaGetSymbolAddress((void**)&WvTs, g_WvTs);
    cudaGetSymbolAddress((void**)&Wqs, g_Wqs);
    cudaGetSymbolAddress((void**)&Kf, g_Kf);     cudaGetSymbolAddress((void**)&Vf, g_Vf);
    cudaGetSymbolAddress((void**)&S, g_S);
    cudaGetSymbolAddress((void**)&s, g_s);       cudaGetSymbolAddress((void**)&r, g_r);
    cudaGetSymbolAddress((void**)&Mh, g_Mh);     cudaGetSymbolAddress((void**)&Ml, g_Ml);
    cudaGetSymbolAddress((void**)&W2Ts, g_W2Ts);

    cudaFuncSetAttribute(gemm_hmma, cudaFuncAttributeMaxDynamicSharedMemorySize, GEMM_DSMEM);

    const long long nBS = (long long)BS * Dd;       // 16M
    const long long dd  = (long long)Dd * Dd;       // 1M
    const long long sd  = (long long)Sq * Dd;       // 4M

    // 0) input conversion (x -> fp16 single plane)
    conv_f16v<<<(unsigned)(nBS / 4 / 256), 256>>>((const float4*)x, (__half2*)xh, nBS / 4);
    transpose_conv_f16<<<dim3(Dd / 32, Dd / 32), dim3(32, 8)>>>(Wk, WkTs, Dd, Dd);
    transpose_conv_f16<<<dim3(Dd / 32, Dd / 32), dim3(32, 8)>>>(Wv, WvTs, Dd, Dd);
    conv_f16<<<(unsigned)((dd + 255) / 256), 256>>>(Wq, Wqs, dd);

    // 1) K = x@Wk + bk ; V = x@Wv + bv  -> fp32, single-pass fp16
    gemm_hmma<<<dim3(Dd / 256, BS / 128, 1), 256, GEMM_DSMEM>>>(
        xh, nullptr, WkTs, bk, Kf, nullptr, nullptr, Dd, Dd, 0, 0, 0, 0);
    gemm_hmma<<<dim3(Dd / 256, BS / 128, 1), 256, GEMM_DSMEM>>>(
        xh, nullptr, WvTs, bv, Vf, nullptr, nullptr, Dd, Dd, 0, 0, 0, 0);

    // 2) s_b = irfft( sum_t rfft(k_t) * rfft(v_t) )
    zero_S<<<(Bsz * 513 * 2 + 255) / 256, 256>>>(S, Bsz * 513 * 2);
    bind_fft<<<dim3(Sq / TOKC, Bsz), 256>>>(Kf, Vf, S);
    irfft_s<<<Bsz, 256>>>(S, s);

    // 3) M_b (fp16 hi/lo), r_b = bq @ M_b
    build_M_f16<<<dim3(Dd / 256, Dd, Bsz), 256>>>(s, Mh, Ml);
    compute_r<<<dim3(Dd / 256, Bsz), 256>>>(s, bq, r);

    // 4) W2T_b = M_b @ Wq^T -> fp16 single (2-pass on M)
    gemm_hmma<<<dim3(Dd / 256, Dd / 128, Bsz), 256, GEMM_DSMEM>>>(
        Mh, Ml, Wqs, nullptr, nullptr, W2Ts, nullptr, Dd, Dd, dd, 0, 0, dd);

    // 5) out_b = x_b @ W2_b + r_b  (single-pass fp16, fp32 out)
    gemm_hmma<<<dim3(Dd / 256, Sq / 128, Bsz), 256, GEMM_DSMEM>>>(
        xh, nullptr, W2Ts, r, out, nullptr, nullptr, Dd, Dd, sd, dd, Dd, sd);
}

// round 9
// speedup vs baseline: 2.9039x; 1.0981x over previous
#include <cuda_runtime.h>
#include <cuda_fp16.h>
#include <stdint.h>

#define Bsz 4
#define Sq  4096
#define Dd  1024
#define BS  (Bsz * Sq)   // 16384

// ---------------- scratch (device globals — allocation is forbidden) ----------------
__device__ __align__(256) __half g_xh[(long long)BS * Dd];
__device__ __align__(256) __half g_WkTs[Dd * Dd];
__device__ __align__(256) __half g_WvTs[Dd * Dd];
__device__ __align__(256) __half g_Wqs[Dd * Dd];
__device__ __align__(256) float  g_Kf[(long long)BS * Dd];
__device__ __align__(256) float  g_Vf[(long long)BS * Dd];
__device__ __align__(256) float  g_S[Bsz * 513 * 2];
__device__ __align__(256) float  g_s[Bsz * Dd];
__device__ __align__(256) float  g_r[Bsz * Dd];
__device__ __align__(256) __half g_Mh[(long long)Bsz * Dd * Dd];
__device__ __align__(256) __half g_Ml[(long long)Bsz * Dd * Dd];
__device__ __align__(256) __half g_W2Ts[(long long)Bsz * Dd * Dd];

// ---------------- PTX helpers ----------------
__device__ __forceinline__ uint32_t smem_u32(const void* p) {
    uint32_t a;
    asm("{ .reg .u64 t; cvta.to.shared.u64 t, %1; cvt.u32.u64 %0, t; }" : "=r"(a) : "l"(p));
    return a;
}
__device__ __forceinline__ void cp16(uint32_t dst, const void* src) {
    asm volatile("cp.async.cg.shared.global [%0], [%1], 16;" :: "r"(dst), "l"(src));
}
__device__ __forceinline__ void cp_commit() { asm volatile("cp.async.commit_group;" ::: "memory"); }
__device__ __forceinline__ void cp_wait1()  { asm volatile("cp.async.wait_group 1;" ::: "memory"); }
__device__ __forceinline__ void cp_wait0()  { asm volatile("cp.async.wait_group 0;" ::: "memory"); }

__device__ __forceinline__ void ldsm_x4(uint32_t& r0, uint32_t& r1, uint32_t& r2, uint32_t& r3,
                                        uint32_t addr) {
    asm volatile("ldmatrix.sync.aligned.m8n8.x4.shared.b16 {%0,%1,%2,%3}, [%4];"
                 : "=r"(r0), "=r"(r1), "=r"(r2), "=r"(r3) : "r"(addr));
}
__device__ __forceinline__ void mma_fp16(float& c0, float& c1, float& c2, float& c3,
                                         uint32_t a0, uint32_t a1, uint32_t a2, uint32_t a3,
                                         uint32_t b0, uint32_t b1) {
    asm volatile(
        "mma.sync.aligned.m16n8k16.row.col.f32.f16.f16.f32 "
        "{%0,%1,%2,%3}, {%4,%5,%6,%7}, {%8,%9}, {%0,%1,%2,%3};"
        : "+f"(c0), "+f"(c1), "+f"(c2), "+f"(c3)
        : "r"(a0), "r"(a1), "r"(a2), "r"(a3), "r"(b0), "r"(b1));
}

// ---------------- fp16 HMMA GEMM: C[M,N] = (Ah [+Al]) @ Bs^T (+bias[n]) ----------------
// CTA tile 128(M) x 128(N) x 64(K), 128 threads = 4 warps (2 M x 2 N), warp tile 64x64.
// 2 CTAs/SM. SMEM row = 128B; 16B chunk c at slot c ^ (row & 7): conflict-free.
// Al == nullptr -> single-pass (A plane1 slot elided, B moves down).
// Output: Cf fp32 | (Ch,Cl) hi/lo fp16 | Ch single fp16.
#define STG1 32768                    // single-pass stage: A 16K + B 16K
#define STG2 49152                    // 2-pass stage:     A 32K + B 16K
#define DSMEM1 (2 * STG1)             // 65536
#define DSMEM2 (2 * STG2)             // 98304

__global__ __launch_bounds__(128, 2) void gemm_hmma(
    const __half* __restrict__ Ah, const __half* __restrict__ Al,
    const __half* __restrict__ Bs,
    const float* __restrict__ bias, float* __restrict__ Cf,
    __half* __restrict__ Ch, __half* __restrict__ Cl,
    int N, int Ktot,
    long long sA, long long sB, long long sBias, long long sC)
{
    extern __shared__ __align__(128) char smem[];
    const int tid = threadIdx.x;
    const int wid = tid >> 5, lid = tid & 31;
    const int bz = blockIdx.z;
    const long long bm = (long long)blockIdx.y * 128;
    const long long bn = (long long)blockIdx.x * 128;

    const __half* gA0 = Ah + bz * sA + bm * Ktot;
    const __half* gA1 = Al ? Al + bz * sA + bm * Ktot : nullptr;
    const __half* gB = Bs + bz * sB + bn * Ktot;
    const float* biasp = bias ? bias + bz * sBias : nullptr;

    const uint32_t b_off = gA1 ? 32768 : 16384;
    const uint32_t stg   = gA1 ? STG2 : STG1;

    const uint32_t sb = smem_u32(smem);
    const int wm = (wid & 1) * 64;
    const int wn = (wid >> 1) * 64;

    float acc[4][8][4];
    #pragma unroll
    for (int a = 0; a < 4; a++)
        #pragma unroll
        for (int b = 0; b < 8; b++)
            #pragma unroll
            for (int c = 0; c < 4; c++) acc[a][b][c] = 0.f;

    auto load_chunk = [&](int p, int k0) {
        const uint32_t buf = sb + p * stg;
        // A plane 0: 128 rows x 8 chunks = 1024 -> 8 iters of 128
        #pragma unroll
        for (int it = 0; it < 8; it++) {
            int id = tid + it * 128;
            int r = id >> 3, c = id & 7;
            cp16(buf + r * 128 + (((c ^ r) & 7) << 4),
                 gA0 + (long long)r * Ktot + k0 + c * 8);
        }
        if (gA1) {
            #pragma unroll
            for (int it = 0; it < 8; it++) {
                int id = tid + it * 128;
                int r = id >> 3, c = id & 7;
                cp16(buf + 16384 + r * 128 + (((c ^ r) & 7) << 4),
                     gA1 + (long long)r * Ktot + k0 + c * 8);
            }
        }
        // B: 128 rows x 8 chunks = 1024 -> 8 iters
        #pragma unroll
        for (int it = 0; it < 8; it++) {
            int id = tid + it * 128;
            int r = id >> 3, c = id & 7;
            cp16(buf + b_off + r * 128 + ((c ^ (r & 7)) << 4),
                 gB + (long long)r * Ktot + k0 + c * 8);
        }
        cp_commit();
    };

    const int nc = Ktot >> 6;
    load_chunk(0, 0);

    const int a_row = wm + (lid & 15);
    const int a_hi  = lid >> 4;
    const int b_row = wn + (lid & 7) + ((lid >> 4) & 1) * 8;
    const int b_hi  = (lid >> 3) & 1;

    for (int i = 0; i < nc; i++) {
        if (i + 1 < nc) { load_chunk((i + 1) & 1, (i + 1) << 6); cp_wait1(); }
        else            { cp_wait0(); }
        __syncthreads();

        const uint32_t buf = sb + (i & 1) * stg;
        #pragma unroll
        for (int kk = 0; kk < 4; kk++) {
            uint32_t Af0[4][4];
            #pragma unroll
            for (int mb = 0; mb < 4; mb++) {
                int r = a_row + mb * 16;
                int c = kk * 2 + a_hi;
                ldsm_x4(Af0[mb][0], Af0[mb][1], Af0[mb][2], Af0[mb][3],
                        buf + r * 128 + ((c ^ (r & 7)) << 4));
            }
            uint32_t Bf[4][4];
            #pragma unroll
            for (int nq = 0; nq < 4; nq++) {
                int r = b_row + nq * 16;
                int c = kk * 2 + b_hi;
                ldsm_x4(Bf[nq][0], Bf[nq][1], Bf[nq][2], Bf[nq][3],
                        buf + b_off + r * 128 + ((c ^ (r & 7)) << 4));
            }
            #pragma unroll
            for (int mb = 0; mb < 4; mb++)
                #pragma unroll
                for (int nq = 0; nq < 4; nq++)
                    #pragma unroll
                    for (int half = 0; half < 2; half++) {
                        float* c = acc[mb][nq * 2 + half];
                        mma_fp16(c[0], c[1], c[2], c[3],
                                 Af0[mb][0], Af0[mb][1], Af0[mb][2], Af0[mb][3],
                                 Bf[nq][half * 2], Bf[nq][half * 2 + 1]);
                    }
            if (gA1) {
                uint32_t Af1[4][4];
                #pragma unroll
                for (int mb = 0; mb < 4; mb++) {
                    int r = a_row + mb * 16;
                    int c = kk * 2 + a_hi;
                    ldsm_x4(Af1[mb][0], Af1[mb][1], Af1[mb][2], Af1[mb][3],
                            buf + 16384 + r * 128 + ((c ^ (r & 7)) << 4));
                }
                #pragma unroll
                for (int mb = 0; mb < 4; mb++)
                    #pragma unroll
                    for (int nq = 0; nq < 4; nq++)
                        #pragma unroll
                        for (int half = 0; half < 2; half++) {
                            float* c = acc[mb][nq * 2 + half];
                            mma_fp16(c[0], c[1], c[2], c[3],
                                     Af1[mb][0], Af1[mb][1], Af1[mb][2], Af1[mb][3],
                                     Bf[nq][half * 2], Bf[nq][half * 2 + 1]);
                        }
            }
        }
        __syncthreads();
    }

    const int er = lid >> 2;
    const int ec = (lid & 3) * 2;
    #pragma unroll
    for (int mb = 0; mb < 4; mb++) {
        #pragma unroll
        for (int nb = 0; nb < 8; nb++) {
            const float* c = acc[mb][nb];
            long long col = bn + wn + nb * 8 + ec;
            float bx = 0.f, by = 0.f;
            if (biasp) { bx = biasp[col]; by = biasp[col + 1]; }
            long long r0 = bm + wm + mb * 16 + er;
            float v0 = c[0] + bx, v1 = c[1] + by;
            float v2 = c[2] + bx, v3 = c[3] + by;
            if (Cf) {
                float* Cb = Cf + bz * sC;
                *reinterpret_cast<float2*>(Cb + r0 * N + col) = make_float2(v0, v1);
                *reinterpret_cast<float2*>(Cb + (r0 + 8) * N + col) = make_float2(v2, v3);
            } else if (Cl) {
                __half h0 = __float2half(v0), h1 = __float2half(v1);
                __half h2 = __float2half(v2), h3 = __float2half(v3);
                __half2 hp0 = { h0, h1 }, hp1 = { h2, h3 };
                __half2 lp0 = { __float2half(v0 - __half2float(h0)),
                                __float2half(v1 - __half2float(h1)) };
                __half2 lp1 = { __float2half(v2 - __half2float(h2)),
                                __float2half(v3 - __half2float(h3)) };
                __half* Hb = Ch + bz * sC;
                __half* Lb = Cl + bz * sC;
                *reinterpret_cast<__half2*>(Hb + r0 * N + col) = hp0;
                *reinterpret_cast<__half2*>(Hb + (r0 + 8) * N + col) = hp1;
                *reinterpret_cast<__half2*>(Lb + r0 * N + col) = lp0;
                *reinterpret_cast<__half2*>(Lb + (r0 + 8) * N + col) = lp1;
            } else {
                __half2 s0 = { __float2half(v0), __float2half(v1) };
                __half2 s1 = { __float2half(v2), __float2half(v3) };
                __half* Hb = Ch + bz * sC;
                *reinterpret_cast<__half2*>(Hb + r0 * N + col) = s0;
                *reinterpret_cast<__half2*>(Hb + (r0 + 8) * N + col) = s1;
            }
        }
    }
}

// ---------------- FFT machinery (radix-4 Stockham, N=1024, 256 threads) ----------------
#define FPAD(i) ((i) + ((i) >> 5))

__device__ __forceinline__ void fft1024_stages(
    float* br0, float* bi0, float* br1, float* bi1,
    const float* twr, const float* twi, int tid, int inv)
{
    float *sr = br0, *si = bi0, *dr = br1, *di = bi1;
    const int Ls[5] = {256, 64, 16, 4, 1};
    const int Ms[5] = {1, 4, 16, 64, 256};
    #pragma unroll
    for (int st = 0; st < 5; st++) {
        const int l = Ls[st], m = Ms[st];
        int j = tid / m, k = tid - j * m;
        int ti = j * (256 / l);
        float w1r = twr[ti], w1i = twi[ti];
        float w2r = w1r * w1r - w1i * w1i, w2i = 2.f * w1r * w1i;
        float w3r = w2r * w1r - w2i * w1i, w3i = w2r * w1i + w2i * w1r;
        int i0 = k + m * j;
        float c0r = sr[FPAD(i0)],             c0i = si[FPAD(i0)];
        float c1r = sr[FPAD(i0 + m * l)],     c1i = si[FPAD(i0 + m * l)];
        float c2r = sr[FPAD(i0 + 2 * m * l)], c2i = si[FPAD(i0 + 2 * m * l)];
        float c3r = sr[FPAD(i0 + 3 * m * l)], c3i = si[FPAD(i0 + 3 * m * l)];
        float t0r = c0r + c2r, t0i = c0i + c2i;
        float t1r = c0r - c2r, t1i = c0i - c2i;
        float t2r = c1r + c3r, t2i = c1i + c3i;
        float t3r = c1r - c3r, t3i = c1i - c3i;
        float u0r = t0r + t2r, u0i = t0i + t2i;
        float u2r = t0r - t2r, u2i = t0i - t2i;
        float u1r, u1i, u3r, u3i;
        if (!inv) { u1r = t1r + t3i; u1i = t1i - t3r; u3r = t1r - t3i; u3i = t1i + t3r; }
        else      { u1r = t1r - t3i; u1i = t1i + t3r; u3r = t1r + t3i; u3i = t1i - t3r; }
        int o = k + 4 * m * j;
        dr[FPAD(o)]         = u0r;                    di[FPAD(o)]         = u0i;
        dr[FPAD(o + m)]     = w1r * u1r - w1i * u1i;  di[FPAD(o + m)]     = w1r * u1i + w1i * u1r;
        dr[FPAD(o + 2 * m)] = w2r * u2r - w2i * u2i;  di[FPAD(o + 2 * m)] = w2r * u2i + w2i * u2r;
        dr[FPAD(o + 3 * m)] = w3r * u3r - w3i * u3i;  di[FPAD(o + 3 * m)] = w3r * u3i + w3i * u3r;
        __syncthreads();
        float* t;
        t = sr; sr = dr; dr = t;
        t = si; si = di; di = t;
    }
}

#define TOKC 16

__global__ __launch_bounds__(256) void bind_fft(
    const float* __restrict__ Kf, const float* __restrict__ Vf, float* __restrict__ Sacc)
{
    __shared__ float Ar0[1056], Ai0[1056], Ar1[1056], Ai1[1056];
    __shared__ float twr[256], twi[256];
    const int tid = threadIdx.x;
    const int b = blockIdx.y;
    const long long base = ((long long)b * Sq + (long long)blockIdx.x * TOKC) * Dd;

    {
        float sv, cv;
        __sincosf(-6.28318530717958647692f * (float)tid / 1024.f, &sv, &cv);
        twr[tid] = cv; twi[tid] = sv;
    }
    float aR0 = 0.f, aI0 = 0.f, aR1 = 0.f, aI1 = 0.f, aR2 = 0.f;

    for (int tok = 0; tok < TOKC; tok++) {
        const float* kr = Kf + base + (long long)tok * Dd;
        const float* vr = Vf + base + (long long)tok * Dd;
        __syncthreads();
        #pragma unroll
        for (int q = 0; q < 4; q++) {
            int i = tid + 256 * q;
            Ar0[FPAD(i)] = kr[i];
            Ai0[FPAD(i)] = vr[i];
        }
        __syncthreads();
        fft1024_stages(Ar0, Ai0, Ar1, Ai1, twr, twi, tid, 0);

        #pragma unroll
        for (int h = 0; h < 2; h++) {
            int f = tid + h * 256;
            int nf = (1024 - f) & 1023;
            float Zr = Ar1[FPAD(f)],  Zi = Ai1[FPAD(f)];
            float Br = Ar1[FPAD(nf)], Bi = Ai1[FPAD(nf)];
            float Kr_ = 0.5f * (Zr + Br), Ki_ = 0.5f * (Zi - Bi);
            float Vr_ = 0.5f * (Zi + Bi), Vi_ = 0.5f * (Br - Zr);
            float Pr = Kr_ * Vr_ - Ki_ * Vi_;
            float Pi = Kr_ * Vi_ + Ki_ * Vr_;
            if (h == 0) { aR0 += Pr; aI0 += Pi; }
            else        { aR1 += Pr; aI1 += Pi; }
        }
        if (tid == 0) {
            float Zr = Ar1[FPAD(512)], Zi = Ai1[FPAD(512)];
            aR2 += Zr * Zi;
        }
    }
    float* Sb = Sacc + b * 513 * 2;
    atomicAdd(&Sb[tid * 2 + 0], aR0);
    atomicAdd(&Sb[tid * 2 + 1], aI0);
    atomicAdd(&Sb[(tid + 256) * 2 + 0], aR1);
    atomicAdd(&Sb[(tid + 256) * 2 + 1], aI1);
    if (tid == 0) atomicAdd(&Sb[512 * 2 + 0], aR2);
}

__global__ __launch_bounds__(256) void irfft_s(const float* __restrict__ Sacc,
                                               float* __restrict__ s)
{
    __shared__ float Ar0[1056], Ai0[1056], Ar1[1056], Ai1[1056];
    __shared__ float twr[256], twi[256];
    const int tid = threadIdx.x;
    const int b = blockIdx.x;
    const float* Sb = Sacc + b * 513 * 2;
    {
        float sv, cv;
        __sincosf(6.28318530717958647692f * (float)tid / 1024.f, &sv, &cv);
        twr[tid] = cv; twi[tid] = sv;
    }
    #pragma unroll
    for (int q = 0; q < 4; q++) {
        int i = tid + 256 * q;
        float re, im;
        if (i <= 512) { re = Sb[i * 2]; im = Sb[i * 2 + 1]; }
        else          { re = Sb[(1024 - i) * 2]; im = -Sb[(1024 - i) * 2 + 1]; }
        Ar0[FPAD(i)] = re;
        Ai0[FPAD(i)] = im;
    }
    __syncthreads();
    fft1024_stages(Ar0, Ai0, Ar1, Ai1, twr, twi, tid, 1);
    #pragma unroll
    for (int q = 0; q < 4; q++) {
        int i = tid + 256 * q;
        s[b * Dd + i] = Ar1[FPAD(i)] * (1.f / 1024.f);
    }
}

// ---------------- prep kernels ----------------
__global__ void zero_S(float* p, int n)
{
    int i = blockIdx.x * 256 + threadIdx.x;
    if (i < n) p[i] = 0.f;
}

__global__ void conv_f16v(const float4* __restrict__ x, __half2* __restrict__ h, long long n4)
{
    long long i = (long long)blockIdx.x * blockDim.x + threadIdx.x;
    if (i < n4) {
        float4 v = x[i];
        h[i * 2 + 0] = __half2{__float2half(v.x), __float2half(v.y)};
        h[i * 2 + 1] = __half2{__float2half(v.z), __float2half(v.w)};
    }
}

__global__ void conv_f16(const float* __restrict__ s, __half* __restrict__ d, long long n)
{
    long long i = (long long)blockIdx.x * blockDim.x + threadIdx.x;
    if (i < n) d[i] = __float2half(s[i]);
}

__global__ void transpose_conv_f16(const float* __restrict__ src, __half* __restrict__ dst,
                                   int R, int C)
{
    __shared__ float t[32][33];
    int c0 = blockIdx.x * 32, r0 = blockIdx.y * 32;
    int tx = threadIdx.x, ty = threadIdx.y;
    #pragma unroll
    for (int k = 0; k < 32; k += 8)
        t[ty + k][tx] = src[(long long)(r0 + ty + k) * C + c0 + tx];
    __syncthreads();
    #pragma unroll
    for (int k = 0; k < 32; k += 8)
        dst[(long long)(c0 + ty + k) * R + r0 + tx] = __float2half(t[tx][ty + k]);
}

__global__ void build_M_f16(const float* __restrict__ s,
                            __half* __restrict__ h, __half* __restrict__ l)
{
    int b = blockIdx.z, k = blockIdx.y;
    int n = blockIdx.x * 256 + threadIdx.x;
    float v = s[b * Dd + ((k + n) & (Dd - 1))];
    __half hi = __float2half(v);
    long long o = ((long long)b << 20) + ((long long)k << 10) + n;
    h[o] = hi;
    l[o] = __float2half(v - __half2float(hi));
}

__global__ void compute_r(const float* __restrict__ s, const float* __restrict__ bq,
                          float* __restrict__ r)
{
    int b = blockIdx.y;
    int n = blockIdx.x * 256 + threadIdx.x;
    float acc = 0.f;
    for (int m = 0; m < Dd; m++)
        acc += bq[m] * s[b * Dd + ((m + n) & (Dd - 1))];
    r[b * Dd + n] = acc;
}

// ---------------- launcher ----------------
extern "C" void kernel_launch(void* const* d_in, const int* in_sizes, int n_in,
                              void* d_out, int out_size)
{
    const float* x  = (const float*)d_in[0];
    const float* Wq = (const float*)d_in[1];
    const float* bq = (const float*)d_in[2];
    const float* Wk = (const float*)d_in[3];
    const float* bk = (const float*)d_in[4];
    const float* Wv = (const float*)d_in[5];
    const float* bv = (const float*)d_in[6];
    float* out = (float*)d_out;

    __half *xh, *WkTs, *WvTs, *Wqs, *Mh, *Ml, *W2Ts;
    float *Kf, *Vf, *S, *s, *r;
    cudaGetSymbolAddress((void**)&xh, g_xh);
    cudaGetSymbolAddress((void**)&WkTs, g_WkTs); cudaGetSymbolAddress((void**)&WvTs, g_WvTs);
    cudaGetSymbolAddress((void**)&Wqs, g_Wqs);
    cudaGetSymbolAddress((void**)&Kf, g_Kf);     cudaGetSymbolAddress((void**)&Vf, g_Vf);
    cudaGetSymbolAddress((void**)&S, g_S);
    cudaGetSymbolAddress((void**)&s, g_s);       cudaGetSymbolAddress((void**)&r, g_r);
    cudaGetSymbolAddress((void**)&Mh, g_Mh);     cudaGetSymbolAddress((void**)&Ml, g_Ml);
    cudaGetSymbolAddress((void**)&W2Ts, g_W2Ts);

    cudaFuncSetAttribute(gemm_hmma, cudaFuncAttributeMaxDynamicSharedMemorySize, DSMEM2);

    const long long nBS = (long long)BS * Dd;       // 16M
    const long long dd  = (long long)Dd * Dd;       // 1M
    const long long sd  = (long long)Sq * Dd;       // 4M

    // 0) input conversion (x -> fp16 single plane)
    conv_f16v<<<(unsigned)(nBS / 4 / 256), 256>>>((const float4*)x, (__half2*)xh, nBS / 4);
    transpose_conv_f16<<<dim3(Dd / 32, Dd / 32), dim3(32, 8)>>>(Wk, WkTs, Dd, Dd);
    transpose_conv_f16<<<dim3(Dd / 32, Dd / 32), dim3(32, 8)>>>(Wv, WvTs, Dd, Dd);
    conv_f16<<<(unsigned)((dd + 255) / 256), 256>>>(Wq, Wqs, dd);

    // 1) K = x@Wk + bk ; V = x@Wv + bv  -> fp32, single-pass fp16
    gemm_hmma<<<dim3(Dd / 128, BS / 128, 1), 128, DSMEM1>>>(
        xh, nullptr, WkTs, bk, Kf, nullptr, nullptr, Dd, Dd, 0, 0, 0, 0);
    gemm_hmma<<<dim3(Dd / 128, BS / 128, 1), 128, DSMEM1>>>(
        xh, nullptr, WvTs, bv, Vf, nullptr, nullptr, Dd, Dd, 0, 0, 0, 0);

    // 2) s_b = irfft( sum_t rfft(k_t) * rfft(v_t) )
    zero_S<<<(Bsz * 513 * 2 + 255) / 256, 256>>>(S, Bsz * 513 * 2);
    bind_fft<<<dim3(Sq / TOKC, Bsz), 256>>>(Kf, Vf, S);
    irfft_s<<<Bsz, 256>>>(S, s);

    // 3) M_b (fp16 hi/lo), r_b = bq @ M_b
    build_M_f16<<<dim3(Dd / 256, Dd, Bsz), 256>>>(s, Mh, Ml);
    compute_r<<<dim3(Dd / 256, Bsz), 256>>>(s, bq, r);

    // 4) W2T_b = M_b @ Wq^T -> fp16 single (2-pass on M)
    gemm_hmma<<<dim3(Dd / 128, Dd / 128, Bsz), 128, DSMEM2>>>(
        Mh, Ml, Wqs, nullptr, nullptr, W2Ts, nullptr, Dd, Dd, dd, 0, 0, dd);

    // 5) out_b = x_b @ W2_b + r_b  (single-pass fp16, fp32 out)
    gemm_hmma<<<dim3(Dd / 128, Sq / 128, Bsz), 128, DSMEM1>>>(
        xh, nullptr, W2Ts, r, out, nullptr, nullptr, Dd, Dd, sd, dd, Dd, sd);
}

// round 10
// speedup vs baseline: 3.2874x; 1.1321x over previous
#include <cuda_runtime.h>
#include <cuda_fp16.h>
#include <stdint.h>

#define Bsz 4
#define Sq  4096
#define Dd  1024
#define BS  (Bsz * Sq)   // 16384

// ---------------- scratch (device globals — allocation is forbidden) ----------------
__device__ __align__(256) __half g_xh[(long long)BS * Dd];
__device__ __align__(256) __half g_WkTs[Dd * Dd];
__device__ __align__(256) __half g_WvTs[Dd * Dd];
__device__ __align__(256) __half g_Kh[(long long)BS * Dd];
__device__ __align__(256) __half g_Vh[(long long)BS * Dd];
__device__ __align__(256) float  g_S[Bsz * 513 * 2];
__device__ __align__(256) float  g_s[Bsz * Dd];
__device__ __align__(256) float  g_r[Bsz * Dd];
__device__ __align__(256) __half g_W2tmp[(long long)Bsz * Dd * Dd];  // [b][d][n]
__device__ __align__(256) __half g_W2Ts[(long long)Bsz * Dd * Dd];   // [b][n][d]

// ---------------- PTX helpers ----------------
__device__ __forceinline__ uint32_t smem_u32(const void* p) {
    uint32_t a;
    asm("{ .reg .u64 t; cvta.to.shared.u64 t, %1; cvt.u32.u64 %0, t; }" : "=r"(a) : "l"(p));
    return a;
}
__device__ __forceinline__ void cp16(uint32_t dst, const void* src) {
    asm volatile("cp.async.cg.shared.global [%0], [%1], 16;" :: "r"(dst), "l"(src));
}
__device__ __forceinline__ void cp_commit() { asm volatile("cp.async.commit_group;" ::: "memory"); }
__device__ __forceinline__ void cp_wait1()  { asm volatile("cp.async.wait_group 1;" ::: "memory"); }
__device__ __forceinline__ void cp_wait0()  { asm volatile("cp.async.wait_group 0;" ::: "memory"); }

__device__ __forceinline__ void ldsm_x4(uint32_t& r0, uint32_t& r1, uint32_t& r2, uint32_t& r3,
                                        uint32_t addr) {
    asm volatile("ldmatrix.sync.aligned.m8n8.x4.shared.b16 {%0,%1,%2,%3}, [%4];"
                 : "=r"(r0), "=r"(r1), "=r"(r2), "=r"(r3) : "r"(addr));
}
__device__ __forceinline__ void mma_fp16(float& c0, float& c1, float& c2, float& c3,
                                         uint32_t a0, uint32_t a1, uint32_t a2, uint32_t a3,
                                         uint32_t b0, uint32_t b1) {
    asm volatile(
        "mma.sync.aligned.m16n8k16.row.col.f32.f16.f16.f32 "
        "{%0,%1,%2,%3}, {%4,%5,%6,%7}, {%8,%9}, {%0,%1,%2,%3};"
        : "+f"(c0), "+f"(c1), "+f"(c2), "+f"(c3)
        : "r"(a0), "r"(a1), "r"(a2), "r"(a3), "r"(b0), "r"(b1));
}

// ---------------- fp16 HMMA GEMM: C[M,N] = Ah @ Bs^T (+bias[n]) ----------------
// CTA tile 128x128x64, 128 threads = 4 warps (2x2), warp tile 64x64, 2 CTAs/SM.
// SMEM row = 128B; 16B chunk c at slot c ^ (row & 7): conflict-free.
// Output: Cf fp32 | Ch single fp16.
#define STG1 32768
#define DSMEM1 (2 * STG1)

__global__ __launch_bounds__(128, 2) void gemm_hmma(
    const __half* __restrict__ Ah,
    const __half* __restrict__ Bs,
    const float* __restrict__ bias, float* __restrict__ Cf,
    __half* __restrict__ Ch,
    int N, int Ktot,
    long long sA, long long sB, long long sBias, long long sC)
{
    extern __shared__ __align__(128) char smem[];
    const int tid = threadIdx.x;
    const int wid = tid >> 5, lid = tid & 31;
    const int bz = blockIdx.z;
    const long long bm = (long long)blockIdx.y * 128;
    const long long bn = (long long)blockIdx.x * 128;

    const __half* gA0 = Ah + bz * sA + bm * Ktot;
    const __half* gB = Bs + bz * sB + bn * Ktot;
    const float* biasp = bias ? bias + bz * sBias : nullptr;

    const uint32_t sb = smem_u32(smem);
    const int wm = (wid & 1) * 64;
    const int wn = (wid >> 1) * 64;

    float acc[4][8][4];
    #pragma unroll
    for (int a = 0; a < 4; a++)
        #pragma unroll
        for (int b = 0; b < 8; b++)
            #pragma unroll
            for (int c = 0; c < 4; c++) acc[a][b][c] = 0.f;

    auto load_chunk = [&](int p, int k0) {
        const uint32_t buf = sb + p * STG1;
        #pragma unroll
        for (int it = 0; it < 8; it++) {
            int id = tid + it * 128;
            int r = id >> 3, c = id & 7;
            cp16(buf + r * 128 + (((c ^ r) & 7) << 4),
                 gA0 + (long long)r * Ktot + k0 + c * 8);
        }
        #pragma unroll
        for (int it = 0; it < 8; it++) {
            int id = tid + it * 128;
            int r = id >> 3, c = id & 7;
            cp16(buf + 16384 + r * 128 + ((c ^ (r & 7)) << 4),
                 gB + (long long)r * Ktot + k0 + c * 8);
        }
        cp_commit();
    };

    const int nc = Ktot >> 6;
    load_chunk(0, 0);

    const int a_row = wm + (lid & 15);
    const int a_hi  = lid >> 4;
    const int b_row = wn + (lid & 7) + ((lid >> 4) & 1) * 8;
    const int b_hi  = (lid >> 3) & 1;

    for (int i = 0; i < nc; i++) {
        if (i + 1 < nc) { load_chunk((i + 1) & 1, (i + 1) << 6); cp_wait1(); }
        else            { cp_wait0(); }
        __syncthreads();

        const uint32_t buf = sb + (i & 1) * STG1;
        #pragma unroll
        for (int kk = 0; kk < 4; kk++) {
            uint32_t Af0[4][4];
            #pragma unroll
            for (int mb = 0; mb < 4; mb++) {
                int r = a_row + mb * 16;
                int c = kk * 2 + a_hi;
                ldsm_x4(Af0[mb][0], Af0[mb][1], Af0[mb][2], Af0[mb][3],
                        buf + r * 128 + ((c ^ (r & 7)) << 4));
            }
            uint32_t Bf[4][4];
            #pragma unroll
            for (int nq = 0; nq < 4; nq++) {
                int r = b_row + nq * 16;
                int c = kk * 2 + b_hi;
                ldsm_x4(Bf[nq][0], Bf[nq][1], Bf[nq][2], Bf[nq][3],
                        buf + 16384 + r * 128 + ((c ^ (r & 7)) << 4));
            }
            #pragma unroll
            for (int mb = 0; mb < 4; mb++)
                #pragma unroll
                for (int nq = 0; nq < 4; nq++)
                    #pragma unroll
                    for (int half = 0; half < 2; half++) {
                        float* c = acc[mb][nq * 2 + half];
                        mma_fp16(c[0], c[1], c[2], c[3],
                                 Af0[mb][0], Af0[mb][1], Af0[mb][2], Af0[mb][3],
                                 Bf[nq][half * 2], Bf[nq][half * 2 + 1]);
                    }
        }
        __syncthreads();
    }

    const int er = lid >> 2;
    const int ec = (lid & 3) * 2;
    #pragma unroll
    for (int mb = 0; mb < 4; mb++) {
        #pragma unroll
        for (int nb = 0; nb < 8; nb++) {
            const float* c = acc[mb][nb];
            long long col = bn + wn + nb * 8 + ec;
            float bx = 0.f, by = 0.f;
            if (biasp) { bx = biasp[col]; by = biasp[col + 1]; }
            long long r0 = bm + wm + mb * 16 + er;
            float v0 = c[0] + bx, v1 = c[1] + by;
            float v2 = c[2] + bx, v3 = c[3] + by;
            if (Cf) {
                float* Cb = Cf + bz * sC;
                *reinterpret_cast<float2*>(Cb + r0 * N + col) = make_float2(v0, v1);
                *reinterpret_cast<float2*>(Cb + (r0 + 8) * N + col) = make_float2(v2, v3);
            } else {
                __half2 s0 = { __float2half(v0), __float2half(v1) };
                __half2 s1 = { __float2half(v2), __float2half(v3) };
                __half* Hb = Ch + bz * sC;
                *reinterpret_cast<__half2*>(Hb + r0 * N + col) = s0;
                *reinterpret_cast<__half2*>(Hb + (r0 + 8) * N + col) = s1;
            }
        }
    }
}

// ---------------- FFT machinery (radix-4 Stockham, N=1024, 256 threads) ----------------
#define FPAD(i) ((i) + ((i) >> 5))

__device__ __forceinline__ void fft1024_stages(
    float* br0, float* bi0, float* br1, float* bi1,
    const float* twr, const float* twi, int tid, int inv)
{
    float *sr = br0, *si = bi0, *dr = br1, *di = bi1;
    const int Ls[5] = {256, 64, 16, 4, 1};
    const int Ms[5] = {1, 4, 16, 64, 256};
    #pragma unroll
    for (int st = 0; st < 5; st++) {
        const int l = Ls[st], m = Ms[st];
        int j = tid / m, k = tid - j * m;
        int ti = j * (256 / l);
        float w1r = twr[ti], w1i = twi[ti];
        float w2r = w1r * w1r - w1i * w1i, w2i = 2.f * w1r * w1i;
        float w3r = w2r * w1r - w2i * w1i, w3i = w2r * w1i + w2i * w1r;
        int i0 = k + m * j;
        float c0r = sr[FPAD(i0)],             c0i = si[FPAD(i0)];
        float c1r = sr[FPAD(i0 + m * l)],     c1i = si[FPAD(i0 + m * l)];
        float c2r = sr[FPAD(i0 + 2 * m * l)], c2i = si[FPAD(i0 + 2 * m * l)];
        float c3r = sr[FPAD(i0 + 3 * m * l)], c3i = si[FPAD(i0 + 3 * m * l)];
        float t0r = c0r + c2r, t0i = c0i + c2i;
        float t1r = c0r - c2r, t1i = c0i - c2i;
        float t2r = c1r + c3r, t2i = c1i + c3i;
        float t3r = c1r - c3r, t3i = c1i - c3i;
        float u0r = t0r + t2r, u0i = t0i + t2i;
        float u2r = t0r - t2r, u2i = t0i - t2i;
        float u1r, u1i, u3r, u3i;
        if (!inv) { u1r = t1r + t3i; u1i = t1i - t3r; u3r = t1r - t3i; u3i = t1i + t3r; }
        else      { u1r = t1r - t3i; u1i = t1i + t3r; u3r = t1r + t3i; u3i = t1i - t3r; }
        int o = k + 4 * m * j;
        dr[FPAD(o)]         = u0r;                    di[FPAD(o)]         = u0i;
        dr[FPAD(o + m)]     = w1r * u1r - w1i * u1i;  di[FPAD(o + m)]     = w1r * u1i + w1i * u1r;
        dr[FPAD(o + 2 * m)] = w2r * u2r - w2i * u2i;  di[FPAD(o + 2 * m)] = w2r * u2i + w2i * u2r;
        dr[FPAD(o + 3 * m)] = w3r * u3r - w3i * u3i;  di[FPAD(o + 3 * m)] = w3r * u3i + w3i * u3r;
        __syncthreads();
        float* t;
        t = sr; sr = dr; dr = t;
        t = si; si = di; di = t;
    }
}

#define TOKC 16

// bind spectrum accumulate: Z = FFT(k + i*v); P = Khat*Vhat; atomic sum into Sacc
__global__ __launch_bounds__(256) void bind_fft(
    const __half* __restrict__ Kh, const __half* __restrict__ Vh, float* __restrict__ Sacc)
{
    __shared__ float Ar0[1056], Ai0[1056], Ar1[1056], Ai1[1056];
    __shared__ float twr[256], twi[256];
    const int tid = threadIdx.x;
    const int b = blockIdx.y;
    const long long base = ((long long)b * Sq + (long long)blockIdx.x * TOKC) * Dd;

    {
        float sv, cv;
        __sincosf(-6.28318530717958647692f * (float)tid / 1024.f, &sv, &cv);
        twr[tid] = cv; twi[tid] = sv;
    }
    float aR0 = 0.f, aI0 = 0.f, aR1 = 0.f, aI1 = 0.f, aR2 = 0.f;

    for (int tok = 0; tok < TOKC; tok++) {
        const __half* kr = Kh + base + (long long)tok * Dd;
        const __half* vr = Vh + base + (long long)tok * Dd;
        __syncthreads();
        #pragma unroll
        for (int q = 0; q < 4; q++) {
            int i = tid + 256 * q;
            Ar0[FPAD(i)] = __half2float(kr[i]);
            Ai0[FPAD(i)] = __half2float(vr[i]);
        }
        __syncthreads();
        fft1024_stages(Ar0, Ai0, Ar1, Ai1, twr, twi, tid, 0);

        #pragma unroll
        for (int h = 0; h < 2; h++) {
            int f = tid + h * 256;
            int nf = (1024 - f) & 1023;
            float Zr = Ar1[FPAD(f)],  Zi = Ai1[FPAD(f)];
            float Br = Ar1[FPAD(nf)], Bi = Ai1[FPAD(nf)];
            float Kr_ = 0.5f * (Zr + Br), Ki_ = 0.5f * (Zi - Bi);
            float Vr_ = 0.5f * (Zi + Bi), Vi_ = 0.5f * (Br - Zr);
            float Pr = Kr_ * Vr_ - Ki_ * Vi_;
            float Pi = Kr_ * Vi_ + Ki_ * Vr_;
            if (h == 0) { aR0 += Pr; aI0 += Pi; }
            else        { aR1 += Pr; aI1 += Pi; }
        }
        if (tid == 0) {
            float Zr = Ar1[FPAD(512)], Zi = Ai1[FPAD(512)];
            aR2 += Zr * Zi;
        }
    }
    float* Sb = Sacc + b * 513 * 2;
    atomicAdd(&Sb[tid * 2 + 0], aR0);
    atomicAdd(&Sb[tid * 2 + 1], aI0);
    atomicAdd(&Sb[(tid + 256) * 2 + 0], aR1);
    atomicAdd(&Sb[(tid + 256) * 2 + 1], aI1);
    if (tid == 0) atomicAdd(&Sb[512 * 2 + 0], aR2);
}

// irfft of the accumulated spectrum -> s_b[1024]
__global__ __launch_bounds__(256) void irfft_s(const float* __restrict__ Sacc,
                                               float* __restrict__ s)
{
    __shared__ float Ar0[1056], Ai0[1056], Ar1[1056], Ai1[1056];
    __shared__ float twr[256], twi[256];
    const int tid = threadIdx.x;
    const int b = blockIdx.x;
    const float* Sb = Sacc + b * 513 * 2;
    {
        float sv, cv;
        __sincosf(6.28318530717958647692f * (float)tid / 1024.f, &sv, &cv);
        twr[tid] = cv; twi[tid] = sv;
    }
    #pragma unroll
    for (int q = 0; q < 4; q++) {
        int i = tid + 256 * q;
        float re, im;
        if (i <= 512) { re = Sb[i * 2]; im = Sb[i * 2 + 1]; }
        else          { re = Sb[(1024 - i) * 2]; im = -Sb[(1024 - i) * 2 + 1]; }
        Ar0[FPAD(i)] = re;
        Ai0[FPAD(i)] = im;
    }
    __syncthreads();
    fft1024_stages(Ar0, Ai0, Ar1, Ai1, twr, twi, tid, 1);
    #pragma unroll
    for (int q = 0; q < 4; q++) {
        int i = tid + 256 * q;
        s[b * Dd + i] = Ar1[FPAD(i)] * (1.f / 1024.f);
    }
}

// W2[d][n] = sum_m Wq[d][m] s_b[(m+n) mod D] = iDFT( Shat_b * conj(What_d) )
// One CTA per Wq row d: forward FFT of the row once, then 4 inverse FFTs (one per batch).
__global__ __launch_bounds__(256) void fft_w2(
    const float* __restrict__ Wq, const float* __restrict__ Sacc,
    __half* __restrict__ W2tmp)
{
    __shared__ float Ar0[1056], Ai0[1056], Ar1[1056], Ai1[1056];
    __shared__ float twf_r[256], twf_i[256], twb_r[256], twb_i[256];
    const int tid = threadIdx.x;
    const int d = blockIdx.x;
    {
        float sv, cv;
        __sincosf(-6.28318530717958647692f * (float)tid / 1024.f, &sv, &cv);
        twf_r[tid] = cv; twf_i[tid] = sv;
        twb_r[tid] = cv; twb_i[tid] = -sv;
    }
    // forward FFT of Wq row d (real input)
    const float* wrow = Wq + (long long)d * Dd;
    #pragma unroll
    for (int q = 0; q < 4; q++) {
        int i = tid + 256 * q;
        Ar0[FPAD(i)] = wrow[i];
        Ai0[FPAD(i)] = 0.f;
    }
    __syncthreads();
    fft1024_stages(Ar0, Ai0, Ar1, Ai1, twf_r, twf_i, tid, 0);

    // save What at this thread's 4 frequencies
    float Wr[4], Wi[4];
    #pragma unroll
    for (int q = 0; q < 4; q++) {
        int f = tid + 256 * q;
        Wr[q] = Ar1[FPAD(f)];
        Wi[q] = Ai1[FPAD(f)];
    }

    for (int b = 0; b < Bsz; b++) {
        const float* Sb = Sacc + b * 513 * 2;
        #pragma unroll
        for (int q = 0; q < 4; q++) {
            int f = tid + 256 * q;
            float Sr, Si;
            if (f <= 512) { Sr = Sb[f * 2]; Si = Sb[f * 2 + 1]; }
            else          { Sr = Sb[(1024 - f) * 2]; Si = -Sb[(1024 - f) * 2 + 1]; }
            // P = Shat * conj(What)
            Ar0[FPAD(f)] = Sr * Wr[q] + Si * Wi[q];
            Ai0[FPAD(f)] = Si * Wr[q] - Sr * Wi[q];
        }
        __syncthreads();
        fft1024_stages(Ar0, Ai0, Ar1, Ai1, twb_r, twb_i, tid, 1);
        __half* dst = W2tmp + ((long long)b << 20) + ((long long)d << 10);
        #pragma unroll
        for (int q = 0; q < 4; q++) {
            int i = tid + 256 * q;
            dst[i] = __float2half(Ar1[FPAD(i)] * (1.f / 1024.f));
        }
    }
}

// ---------------- prep kernels ----------------
__global__ void zero_S(float* p, int n)
{
    int i = blockIdx.x * 256 + threadIdx.x;
    if (i < n) p[i] = 0.f;
}

__global__ void conv_f16v(const float4* __restrict__ x, __half2* __restrict__ h, long long n4)
{
    long long i = (long long)blockIdx.x * blockDim.x + threadIdx.x;
    if (i < n4) {
        float4 v = x[i];
        h[i * 2 + 0] = __half2{__float2half(v.x), __float2half(v.y)};
        h[i * 2 + 1] = __half2{__float2half(v.z), __float2half(v.w)};
    }
}

__global__ void transpose_conv_f16(const float* __restrict__ src, __half* __restrict__ dst,
                                   int R, int C)
{
    __shared__ float t[32][33];
    int c0 = blockIdx.x * 32, r0 = blockIdx.y * 32;
    int tx = threadIdx.x, ty = threadIdx.y;
    #pragma unroll
    for (int k = 0; k < 32; k += 8)
        t[ty + k][tx] = src[(long long)(r0 + ty + k) * C + c0 + tx];
    __syncthreads();
    #pragma unroll
    for (int k = 0; k < 32; k += 8)
        dst[(long long)(c0 + ty + k) * R + r0 + tx] = __float2half(t[tx][ty + k]);
}

// fp16 [R,C] -> [C,R], batched
__global__ void transpose_f16(const __half* __restrict__ s, __half* __restrict__ d,
                              int R, int C, long long sIn, long long sOut)
{
    __shared__ __half t[64][65];
    int b = blockIdx.z;
    s += (long long)b * sIn; d += (long long)b * sOut;
    int c0 = blockIdx.x * 64, r0 = blockIdx.y * 64;
    int tid = threadIdx.x;
    #pragma unroll
    for (int it = 0; it < 8; it++) {
        int id = tid + it * 256;
        int row = id >> 5, cp = (id & 31) * 2;
        __half2 v = *reinterpret_cast<const __half2*>(s + (long long)(r0 + row) * C + c0 + cp);
        t[row][cp] = v.x; t[row][cp + 1] = v.y;
    }
    __syncthreads();
    #pragma unroll
    for (int it = 0; it < 8; it++) {
        int id = tid + it * 256;
        int cc = id >> 5, rp = (id & 31) * 2;
        __half2 v = { t[rp][cc], t[rp + 1][cc] };
        *reinterpret_cast<__half2*>(d + (long long)(c0 + cc) * R + r0 + rp) = v;
    }
}

__global__ void compute_r(const float* __restrict__ s, const float* __restrict__ bq,
                          float* __restrict__ r)
{
    int b = blockIdx.y;
    int n = blockIdx.x * 256 + threadIdx.x;
    float acc = 0.f;
    for (int m = 0; m < Dd; m++)
        acc += bq[m] * s[b * Dd + ((m + n) & (Dd - 1))];
    r[b * Dd + n] = acc;
}

// ---------------- launcher ----------------
extern "C" void kernel_launch(void* const* d_in, const int* in_sizes, int n_in,
                              void* d_out, int out_size)
{
    const float* x  = (const float*)d_in[0];
    const float* Wq = (const float*)d_in[1];
    const float* bq = (const float*)d_in[2];
    const float* Wk = (const float*)d_in[3];
    const float* bk = (const float*)d_in[4];
    const float* Wv = (const float*)d_in[5];
    const float* bv = (const float*)d_in[6];
    float* out = (float*)d_out;

    __half *xh, *WkTs, *WvTs, *Kh, *Vh, *W2tmp, *W2Ts;
    float *S, *s, *r;
    cudaGetSymbolAddress((void**)&xh, g_xh);
    cudaGetSymbolAddress((void**)&WkTs, g_WkTs); cudaGetSymbolAddress((void**)&WvTs, g_WvTs);
    cudaGetSymbolAddress((void**)&Kh, g_Kh);     cudaGetSymbolAddress((void**)&Vh, g_Vh);
    cudaGetSymbolAddress((void**)&S, g_S);
    cudaGetSymbolAddress((void**)&s, g_s);       cudaGetSymbolAddress((void**)&r, g_r);
    cudaGetSymbolAddress((void**)&W2tmp, g_W2tmp);
    cudaGetSymbolAddress((void**)&W2Ts, g_W2Ts);

    cudaFuncSetAttribute(gemm_hmma, cudaFuncAttributeMaxDynamicSharedMemorySize, DSMEM1);

    const long long nBS = (long long)BS * Dd;       // 16M
    const long long dd  = (long long)Dd * Dd;       // 1M
    const long long sd  = (long long)Sq * Dd;       // 4M

    // 0) input conversion
    conv_f16v<<<(unsigned)(nBS / 4 / 256), 256>>>((const float4*)x, (__half2*)xh, nBS / 4);
    transpose_conv_f16<<<dim3(Dd / 32, Dd / 32), dim3(32, 8)>>>(Wk, WkTs, Dd, Dd);
    transpose_conv_f16<<<dim3(Dd / 32, Dd / 32), dim3(32, 8)>>>(Wv, WvTs, Dd, Dd);

    // 1) K = x@Wk + bk ; V = x@Wv + bv  -> fp16 (single plane)
    gemm_hmma<<<dim3(Dd / 128, BS / 128, 1), 128, DSMEM1>>>(
        xh, WkTs, bk, nullptr, Kh, Dd, Dd, 0, 0, 0, 0);
    gemm_hmma<<<dim3(Dd / 128, BS / 128, 1), 128, DSMEM1>>>(
        xh, WvTs, bv, nullptr, Vh, Dd, Dd, 0, 0, 0, 0);

    // 2) Shat_b = sum_t rfft(k_t)*rfft(v_t);  s_b = irfft(Shat_b)
    zero_S<<<(Bsz * 513 * 2 + 255) / 256, 256>>>(S, Bsz * 513 * 2);
    bind_fft<<<dim3(Sq / TOKC, Bsz), 256>>>(Kh, Vh, S);
    irfft_s<<<Bsz, 256>>>(S, s);

    // 3) r_b = bq @ M_b (circulant matvec, direct)
    compute_r<<<dim3(Dd / 256, Bsz), 256>>>(s, bq, r);

    // 4) W2[d][n] = iDFT(Shat_b * conj(rfft(Wq_d))) per row; then transpose to [n][d]
    fft_w2<<<Dd, 256>>>(Wq, S, W2tmp);
    transpose_f16<<<dim3(Dd / 64, Dd / 64, Bsz), 256>>>(W2tmp, W2Ts, Dd, Dd, dd, dd);

    // 5) out_b = x_b @ W2_b + r_b  (fp32 out)
    gemm_hmma<<<dim3(Dd / 128, Sq / 128, Bsz), 128, DSMEM1>>>(
        xh, W2Ts, r, out, nullptr, Dd, Dd, sd, dd, Dd, sd);
}